// round 1
// baseline (speedup 1.0000x reference)
#include <cuda_runtime.h>
#include <cstdint>
#include <cstddef>

#define H 128
#define NTYPE 10
#define NREL 26
#define N_TOTAL 614000
#define MAX_DST 150000

// ---------------- scratch (static device globals; no allocation) ----------------
__device__ float g_buf0[(size_t)N_TOTAL * H];   // layer-0 output
__device__ float g_buf1[(size_t)N_TOTAL * H];   // layer-1 output
__device__ float g_agg[(size_t)MAX_DST * H];    // per-relation aggregation buffer
__device__ float g_deg[MAX_DST];                // per-relation degree buffer
__device__ float g_wsum[2 * NTYPE * H * H];     // summed Wr per (layer, dst type)
__device__ float g_bsum[2 * NTYPE * H];         // summed bias per (layer, dst type)

// dst type of each of the 26 directed relations (compile-time constant memory)
__constant__ int c_rel_dst[NREL] = {1,0,2,0,3,0,4,0,5,0,6,0,7,6,6,5,7,5,5,4,3,4,8,2,9,2};

// ---------------- Wr / bias reduction over relations sharing a dst type ----------------
__global__ void __launch_bounds__(256) wsum_kernel(
    const float* __restrict__ Wr, const float* __restrict__ bl,
    float* __restrict__ wsum, float* __restrict__ bsum)
{
    int layer = blockIdx.x / NTYPE;
    int t = blockIdx.x % NTYPE;
    const float* base = Wr + (size_t)layer * NREL * H * H;
    float* outw = wsum + ((size_t)layer * NTYPE + t) * H * H;
    for (int e = threadIdx.x; e < H * H; e += 256) {
        float a = 0.f;
        #pragma unroll
        for (int r = 0; r < NREL; r++)
            if (c_rel_dst[r] == t) a += base[(size_t)r * H * H + e];
        outw[e] = a;
    }
    if (threadIdx.x < H) {
        float a = 0.f;
        #pragma unroll
        for (int r = 0; r < NREL; r++)
            if (c_rel_dst[r] == t) a += bl[((size_t)layer * NREL + r) * H + threadIdx.x];
        bsum[((size_t)layer * NTYPE + t) * H + threadIdx.x] = a;
    }
}

// ---------------- edge scatter: warp per edge, vector reduction ----------------
__global__ void __launch_bounds__(256) scatter_kernel(
    const float* __restrict__ xsrc, const int* __restrict__ srcI,
    const int* __restrict__ dstI, float* __restrict__ agg,
    float* __restrict__ deg, int nE)
{
    int g = blockIdx.x * blockDim.x + threadIdx.x;
    int e = g >> 5;
    if (e >= nE) return;
    int lane = g & 31;
    int s = __ldg(srcI + e);
    int d = __ldg(dstI + e);
    float4 v = ((const float4*)(xsrc + (size_t)s * H))[lane];
    float* p = agg + (size_t)d * H + lane * 4;
    asm volatile("red.global.add.v4.f32 [%0], {%1,%2,%3,%4};"
                 :: "l"(p), "f"(v.x), "f"(v.y), "f"(v.z), "f"(v.w)
                 : "memory");
    if (lane == 0) atomicAdd(deg + d, 1.0f);
}

// ---------------- 128-wide GEMM: C[M,128] (+)= rowscale(A[M,128]) @ B[128,128] (+bias) ---
// BM=128, BN=128, KC=16, 256 threads, 8x8 per thread, double-buffered smem.
__global__ void __launch_bounds__(256, 2) gemm128(
    const float* __restrict__ A, const float* __restrict__ B,
    const float* __restrict__ deg, const float* __restrict__ bias,
    float* __restrict__ C, int M, int accumulate)
{
    __shared__ float As[2][16][H];
    __shared__ float Bs[2][16][H];
    const int tid = threadIdx.x;
    const int m0 = blockIdx.x * 128;
    const int ty = tid >> 4, tx = tid & 15;
    const int row = ty * 8, col = tx * 8;

    // A-load mapping: thread loads row am = tid/2, k-offset ak = (tid&1)*8, 8 floats
    const int am = tid >> 1;
    const int ak = (tid & 1) * 8;
    const bool avalid = (m0 + am) < M;
    float ascale = 1.0f;
    if (avalid && deg) ascale = 1.0f / fmaxf(deg[m0 + am], 1.0f);
    const float4* Arow = (const float4*)(A + (size_t)(m0 + am) * H);

    // B-load mapping: thread loads float4 idx 2*tid and 2*tid+1 of each 16x128 chunk
    const int bk0 = (2 * tid) >> 5, bn0 = (2 * tid) & 31;
    const int bk1 = (2 * tid + 1) >> 5, bn1 = (2 * tid + 1) & 31;
    const float4* B4 = (const float4*)B;

    float acc[8][8];
    #pragma unroll
    for (int i = 0; i < 8; i++)
        #pragma unroll
        for (int j = 0; j < 8; j++) acc[i][j] = 0.0f;

    float4 pa0, pa1, pb0, pb1;

    // prologue: chunk 0 -> buffer 0
    if (avalid) {
        pa0 = Arow[ak >> 2];
        pa1 = Arow[(ak >> 2) + 1];
    } else { pa0 = make_float4(0.f,0.f,0.f,0.f); pa1 = pa0; }
    pb0 = B4[bk0 * 32 + bn0];
    pb1 = B4[bk1 * 32 + bn1];
    {
        float av[8] = {pa0.x,pa0.y,pa0.z,pa0.w,pa1.x,pa1.y,pa1.z,pa1.w};
        #pragma unroll
        for (int j = 0; j < 8; j++) As[0][ak + j][am] = av[j] * ascale;
        *(float4*)&Bs[0][bk0][bn0 * 4] = pb0;
        *(float4*)&Bs[0][bk1][bn1 * 4] = pb1;
    }
    __syncthreads();

    #pragma unroll
    for (int kc = 0; kc < 8; kc++) {
        const int b = kc & 1;
        if (kc < 7) {   // prefetch next chunk into registers
            const int k0 = (kc + 1) * 16;
            if (avalid) {
                pa0 = Arow[(k0 + ak) >> 2];
                pa1 = Arow[((k0 + ak) >> 2) + 1];
            } else { pa0 = make_float4(0.f,0.f,0.f,0.f); pa1 = pa0; }
            pb0 = B4[(k0 + bk0) * 32 + bn0];
            pb1 = B4[(k0 + bk1) * 32 + bn1];
        }
        #pragma unroll
        for (int kk = 0; kk < 16; kk++) {
            float4 a0 = *(const float4*)&As[b][kk][row];
            float4 a1 = *(const float4*)&As[b][kk][row + 4];
            float4 b0 = *(const float4*)&Bs[b][kk][col];
            float4 b1 = *(const float4*)&Bs[b][kk][col + 4];
            float av[8] = {a0.x,a0.y,a0.z,a0.w,a1.x,a1.y,a1.z,a1.w};
            float bv[8] = {b0.x,b0.y,b0.z,b0.w,b1.x,b1.y,b1.z,b1.w};
            #pragma unroll
            for (int i = 0; i < 8; i++)
                #pragma unroll
                for (int j = 0; j < 8; j++)
                    acc[i][j] += av[i] * bv[j];
        }
        if (kc < 7) {   // stage prefetched chunk into the other buffer
            const int nb = b ^ 1;
            float av[8] = {pa0.x,pa0.y,pa0.z,pa0.w,pa1.x,pa1.y,pa1.z,pa1.w};
            #pragma unroll
            for (int j = 0; j < 8; j++) As[nb][ak + j][am] = av[j] * ascale;
            *(float4*)&Bs[nb][bk0][bn0 * 4] = pb0;
            *(float4*)&Bs[nb][bk1][bn1 * 4] = pb1;
            __syncthreads();
        }
    }

    // epilogue
    #pragma unroll
    for (int i = 0; i < 8; i++) {
        const int m = m0 + row + i;
        if (m < M) {
            float* cp = C + (size_t)m * H + col;
            #pragma unroll
            for (int j = 0; j < 8; j++) {
                float v = acc[i][j];
                if (bias) v += bias[col + j];
                if (accumulate) v += cp[j];
                cp[j] = v;
            }
        }
    }
}

// ---------------- relu over a whole buffer (float4 grid-stride) ----------------
__global__ void relu_kernel(float* __restrict__ x, size_t n4)
{
    size_t i = (size_t)blockIdx.x * blockDim.x + threadIdx.x;
    size_t stride = (size_t)gridDim.x * blockDim.x;
    float4* p = (float4*)x;
    for (; i < n4; i += stride) {
        float4 v = p[i];
        v.x = fmaxf(v.x, 0.f); v.y = fmaxf(v.y, 0.f);
        v.z = fmaxf(v.z, 0.f); v.w = fmaxf(v.w, 0.f);
        p[i] = v;
    }
}

// ---------------- final linear: out[M,64] = X[M,128] @ W[128,64] + b ----------------
__global__ void __launch_bounds__(128) final_kernel(
    const float* __restrict__ X, const float* __restrict__ W,
    const float* __restrict__ b, float* __restrict__ out, int M)
{
    __shared__ float Ws[H * 64];
    __shared__ float bs[64];
    for (int i = threadIdx.x; i < H * 64; i += 128) Ws[i] = W[i];
    if (threadIdx.x < 64) bs[threadIdx.x] = b[threadIdx.x];
    __syncthreads();
    int m = blockIdx.x * 128 + threadIdx.x;
    if (m >= M) return;
    float acc[64];
    #pragma unroll
    for (int j = 0; j < 64; j++) acc[j] = bs[j];
    const float* x = X + (size_t)m * H;
    for (int k = 0; k < H; k++) {
        float xv = x[k];
        #pragma unroll
        for (int j = 0; j < 64; j++) acc[j] += xv * Ws[k * 64 + j];
    }
    float* o = out + (size_t)m * 64;
    #pragma unroll
    for (int j = 0; j < 64; j++) o[j] = acc[j];
}

// ---------------- host orchestration ----------------
static const int NN[NTYPE]   = {50000,2000,80000,10000,2000,150000,120000,100000,60000,40000};
static const int OFFS[NTYPE] = {0,50000,52000,132000,142000,144000,294000,414000,514000,574000};
static const int R_SRC[NREL] = {0,1,0,2,0,3,0,4,0,5,0,6,6,7,5,6,5,7,4,5,4,3,2,8,2,9};
static const int R_DST[NREL] = {1,0,2,0,3,0,4,0,5,0,6,0,7,6,6,5,7,5,5,4,3,4,8,2,9,2};
static const int R_EI[NREL]  = {10,10,11,11,12,12,13,13,14,14,15,15,16,16,17,17,18,18,19,19,20,20,21,21,22,22};
static const int R_FLIP[NREL]= {0,1,0,1,0,1,0,1,0,1,0,1,0,1,0,1,0,1,0,1,0,1,0,1,0,1};

extern "C" void kernel_launch(void* const* d_in, const int* in_sizes, int n_in,
                              void* d_out, int out_size)
{
    const float* Wl   = (const float*)d_in[23];
    const float* bl   = (const float*)d_in[24];
    const float* Wr   = (const float*)d_in[25];
    const float* linW = (const float*)d_in[26];
    const float* linb = (const float*)d_in[27];

    float *buf0, *buf1, *agg, *deg, *wsum, *bsum;
    cudaGetSymbolAddress((void**)&buf0, g_buf0);
    cudaGetSymbolAddress((void**)&buf1, g_buf1);
    cudaGetSymbolAddress((void**)&agg,  g_agg);
    cudaGetSymbolAddress((void**)&deg,  g_deg);
    cudaGetSymbolAddress((void**)&wsum, g_wsum);
    cudaGetSymbolAddress((void**)&bsum, g_bsum);

    wsum_kernel<<<2 * NTYPE, 256>>>(Wr, bl, wsum, bsum);

    const float* cur[NTYPE];
    for (int t = 0; t < NTYPE; t++) cur[t] = (const float*)d_in[t];
    float* bufs[2] = {buf0, buf1};

    for (int layer = 0; layer < 2; layer++) {
        float* outbuf = bufs[layer];

        // self term: out[t] = x[t] @ WrSum[layer,t] + biasSum[layer,t]
        for (int t = 0; t < NTYPE; t++) {
            int M = NN[t];
            gemm128<<<(M + 127) / 128, 256>>>(
                cur[t], wsum + ((size_t)layer * NTYPE + t) * H * H, nullptr,
                bsum + ((size_t)layer * NTYPE + t) * H,
                outbuf + (size_t)OFFS[t] * H, M, 0);
        }

        // neighbor terms: out[d] += (agg/deg) @ Wl[layer,r]
        for (int r = 0; r < NREL; r++) {
            int s = R_SRC[r], d = R_DST[r], ii = R_EI[r];
            const int* ei = (const int*)d_in[ii];
            int E = in_sizes[ii] / 2;
            const int* srcI = R_FLIP[r] ? ei + E : ei;
            const int* dstI = R_FLIP[r] ? ei : ei + E;
            int nd = NN[d];

            cudaMemsetAsync(agg, 0, (size_t)nd * H * sizeof(float), 0);
            cudaMemsetAsync(deg, 0, (size_t)nd * sizeof(float), 0);

            long threads = (long)E * 32;
            scatter_kernel<<<(unsigned)((threads + 255) / 256), 256>>>(
                cur[s], srcI, dstI, agg, deg, E);

            gemm128<<<(nd + 127) / 128, 256>>>(
                agg, Wl + ((size_t)layer * NREL + r) * H * H, deg,
                nullptr, outbuf + (size_t)OFFS[d] * H, nd, 1);
        }

        relu_kernel<<<4096, 256>>>(outbuf, (size_t)N_TOTAL * H / 4);
        for (int t = 0; t < NTYPE; t++) cur[t] = outbuf + (size_t)OFFS[t] * H;
    }

    // final: course nodes only
    final_kernel<<<(NN[0] + 127) / 128, 128>>>(cur[0], linW, linb, (float*)d_out, NN[0]);
}

// round 3
// speedup vs baseline: 1.2981x; 1.2981x over previous
#include <cuda_runtime.h>
#include <cuda_bf16.h>
#include <cstdint>
#include <cstddef>

#define H 128
#define NTYPE 10
#define NREL 26
#define N_TOTAL 614000
#define MAX_DST 150000

// ---------------- scratch ----------------
__device__ float g_buf0[(size_t)N_TOTAL * H];
__device__ float g_buf1[(size_t)N_TOTAL * H];
__device__ float g_agg[(size_t)MAX_DST * H];
__device__ float g_deg[MAX_DST];
__device__ float g_wsum[2 * NTYPE * H * H];
__device__ float g_bsum[2 * NTYPE * H];

__constant__ int c_rel_dst[NREL] = {1,0,2,0,3,0,4,0,5,0,6,0,7,6,6,5,7,5,5,4,3,4,8,2,9,2};

// ---------------- helpers ----------------
__device__ __forceinline__ uint32_t smem_to_u32(const void* p) {
    uint32_t a;
    asm("{ .reg .u64 t; cvta.to.shared.u64 t, %1; cvt.u32.u64 %0, t; }" : "=r"(a) : "l"(p));
    return a;
}

__device__ __forceinline__ void cvt8(const float* v, float scale, uint4& hi, uint4& lo) {
    uint32_t h[4], l[4];
    #pragma unroll
    for (int p = 0; p < 4; p++) {
        float a = v[2*p] * scale, b = v[2*p+1] * scale;
        __nv_bfloat16 ah = __float2bfloat16(a), bh = __float2bfloat16(b);
        float ar = a - __bfloat162float(ah), br = b - __bfloat162float(bh);
        __nv_bfloat16 al = __float2bfloat16(ar), bl2 = __float2bfloat16(br);
        h[p] = (uint32_t)__bfloat16_as_ushort(ah) | ((uint32_t)__bfloat16_as_ushort(bh) << 16);
        l[p] = (uint32_t)__bfloat16_as_ushort(al) | ((uint32_t)__bfloat16_as_ushort(bl2) << 16);
    }
    hi = make_uint4(h[0], h[1], h[2], h[3]);
    lo = make_uint4(l[0], l[1], l[2], l[3]);
}

#define LDMATRIX_X4(r0, r1, r2, r3, addr) \
    asm volatile("ldmatrix.sync.aligned.m8n8.x4.shared.b16 {%0,%1,%2,%3}, [%4];" \
                 : "=r"(r0), "=r"(r1), "=r"(r2), "=r"(r3) : "r"(addr))

#define MMA_BF16(c0, c1, c2, c3, a0, a1, a2, a3, b0, b1) \
    asm volatile("mma.sync.aligned.m16n8k16.row.col.f32.bf16.bf16.f32 " \
                 "{%0,%1,%2,%3}, {%4,%5,%6,%7}, {%8,%9}, {%0,%1,%2,%3};" \
                 : "+f"(c0), "+f"(c1), "+f"(c2), "+f"(c3) \
                 : "r"(a0), "r"(a1), "r"(a2), "r"(a3), "r"(b0), "r"(b1))

// ---------------- bf16 HMMA GEMM: C[M,128] (+)= rowscale(A[M,128]) @ W[128,128] (+bias) --
// 256 threads, 128x128 tile/block, full K=128 staged, split-bf16 3-pass.
// smem layout (bf16, row stride 136 elems = 272B, conflict-free for ldmatrix):
#define A_LD 136
#define SM_AH 0
#define SM_AL 34816
#define SM_BH 69632
#define SM_BL 104448
#define SM_BYTES 139264

__global__ void __launch_bounds__(256, 1) gemm_mma(
    const float* __restrict__ A, const float* __restrict__ W,
    const float* __restrict__ deg, const float* __restrict__ bias,
    float* __restrict__ C, int M, int accumulate)
{
    extern __shared__ char smem[];
    const uint32_t sb = smem_to_u32(smem);
    const int tid = threadIdx.x, lane = tid & 31, wid = tid >> 5;
    const int m0 = blockIdx.x * 128;

    // ---- stage A (rows m0..m0+127) as bf16 hi/lo, deg-scaled ----
    {
        const int r = tid >> 1;              // 0..127
        const int co = (tid & 1) * 64;       // col offset 0 or 64
        const int m = m0 + r;
        __nv_bfloat16* ah = (__nv_bfloat16*)(smem + 0);
        if (m < M) {
            float scale = 1.0f;
            if (deg) scale = 1.0f / fmaxf(deg[m], 1.0f);
            const float4* Ar = (const float4*)(A + (size_t)m * H);
            #pragma unroll
            for (int c = 0; c < 64; c += 8) {
                float4 f0 = Ar[(co + c) >> 2], f1 = Ar[((co + c) >> 2) + 1];
                float v[8] = {f0.x,f0.y,f0.z,f0.w,f1.x,f1.y,f1.z,f1.w};
                uint4 hi, lo;
                cvt8(v, scale, hi, lo);
                *(uint4*)(smem + SM_AH + (size_t)(r * A_LD + co + c) * 2) = hi;
                *(uint4*)(smem + SM_AL + (size_t)(r * A_LD + co + c) * 2) = lo;
            }
        } else {
            uint4 z = make_uint4(0,0,0,0);
            #pragma unroll
            for (int c = 0; c < 64; c += 8) {
                *(uint4*)(smem + SM_AH + (size_t)(r * A_LD + co + c) * 2) = z;
                *(uint4*)(smem + SM_AL + (size_t)(r * A_LD + co + c) * 2) = z;
            }
        }
    }

    // ---- stage W transposed: smem B[n][k], bf16 hi/lo ----
    // gmem W is [k][n] row-major; read coalesced, write 2B scattered (cheap).
    for (int idx = tid; idx < H * H; idx += 256) {
        int k = idx >> 7, n = idx & 127;
        float w = W[idx];
        __nv_bfloat16 wh = __float2bfloat16(w);
        float wr = w - __bfloat162float(wh);
        __nv_bfloat16 wl = __float2bfloat16(wr);
        *(__nv_bfloat16*)(smem + SM_BH + (size_t)(n * A_LD + k) * 2) = wh;
        *(__nv_bfloat16*)(smem + SM_BL + (size_t)(n * A_LD + k) * 2) = wl;
    }
    __syncthreads();

    // ---- warp tiling: 2x4 warps, each warp 64(m) x 32(n) ----
    const int warp_m = (wid >> 2) * 64;
    const int warp_n = (wid & 3) * 32;

    float acc[4][4][4];
    #pragma unroll
    for (int mt = 0; mt < 4; mt++)
        #pragma unroll
        for (int nt = 0; nt < 4; nt++)
            #pragma unroll
            for (int q = 0; q < 4; q++) acc[mt][nt][q] = 0.0f;

    // ldmatrix lane addressing (same pattern for A and B tiles):
    // row = base + (lane & 15), col = k0 + ((lane >> 4) << 3)
    const int lrow = lane & 15;
    const int lcol = (lane >> 4) << 3;

    #pragma unroll
    for (int pass = 0; pass < 3; pass++) {
        const uint32_t abase = sb + (pass == 1 ? SM_AL : SM_AH);
        const uint32_t bbase = sb + (pass == 2 ? SM_BL : SM_BH);
        #pragma unroll
        for (int ks = 0; ks < 8; ks++) {
            const int k0 = ks * 16;
            // B frags: 2 ldmatrix.x4, covering n16 x k16 each
            uint32_t b[8];
            #pragma unroll
            for (int np = 0; np < 2; np++) {
                uint32_t addr = bbase + (uint32_t)(((warp_n + np * 16 + lrow) * A_LD + k0 + lcol) * 2);
                LDMATRIX_X4(b[np*4+0], b[np*4+1], b[np*4+2], b[np*4+3], addr);
            }
            #pragma unroll
            for (int mt = 0; mt < 4; mt++) {
                uint32_t a0, a1, a2, a3;
                uint32_t addr = abase + (uint32_t)(((warp_m + mt * 16 + lrow) * A_LD + k0 + lcol) * 2);
                LDMATRIX_X4(a0, a1, a2, a3, addr);
                // nt mapping: nt = np*2 + half; b-frag = {reg[np*4+half], reg[np*4+2+half]}
                MMA_BF16(acc[mt][0][0], acc[mt][0][1], acc[mt][0][2], acc[mt][0][3], a0, a1, a2, a3, b[0], b[2]);
                MMA_BF16(acc[mt][1][0], acc[mt][1][1], acc[mt][1][2], acc[mt][1][3], a0, a1, a2, a3, b[1], b[3]);
                MMA_BF16(acc[mt][2][0], acc[mt][2][1], acc[mt][2][2], acc[mt][2][3], a0, a1, a2, a3, b[4], b[6]);
                MMA_BF16(acc[mt][3][0], acc[mt][3][1], acc[mt][3][2], acc[mt][3][3], a0, a1, a2, a3, b[5], b[7]);
            }
        }
    }

    // ---- epilogue ----
    const int qrow = lane >> 2;          // 0..7
    const int qcol = (lane & 3) * 2;     // 0,2,4,6
    #pragma unroll
    for (int mt = 0; mt < 4; mt++) {
        #pragma unroll
        for (int half = 0; half < 2; half++) {
            const int m = m0 + warp_m + mt * 16 + qrow + half * 8;
            if (m < M) {
                float* cp = C + (size_t)m * H;
                #pragma unroll
                for (int nt = 0; nt < 4; nt++) {
                    const int c = warp_n + nt * 8 + qcol;
                    float v0 = acc[mt][nt][half * 2 + 0];
                    float v1 = acc[mt][nt][half * 2 + 1];
                    if (accumulate) {
                        asm volatile("red.global.add.v2.f32 [%0], {%1,%2};"
                                     :: "l"(cp + c), "f"(v0), "f"(v1) : "memory");
                    } else {
                        if (bias) { v0 += bias[c]; v1 += bias[c + 1]; }
                        *(float2*)(cp + c) = make_float2(v0, v1);
                    }
                }
            }
        }
    }
}

// ---------------- Wr / bias reduction ----------------
__global__ void __launch_bounds__(256) wsum_kernel(
    const float* __restrict__ Wr, const float* __restrict__ bl,
    float* __restrict__ wsum, float* __restrict__ bsum)
{
    int layer = blockIdx.x / NTYPE;
    int t = blockIdx.x % NTYPE;
    const float* base = Wr + (size_t)layer * NREL * H * H;
    float* outw = wsum + ((size_t)layer * NTYPE + t) * H * H;
    for (int e = threadIdx.x; e < H * H; e += 256) {
        float a = 0.f;
        #pragma unroll
        for (int r = 0; r < NREL; r++)
            if (c_rel_dst[r] == t) a += base[(size_t)r * H * H + e];
        outw[e] = a;
    }
    if (threadIdx.x < H) {
        float a = 0.f;
        #pragma unroll
        for (int r = 0; r < NREL; r++)
            if (c_rel_dst[r] == t) a += bl[((size_t)layer * NREL + r) * H + threadIdx.x];
        bsum[((size_t)layer * NTYPE + t) * H + threadIdx.x] = a;
    }
}

// ---------------- edge scatter ----------------
__global__ void __launch_bounds__(256) scatter_kernel(
    const float* __restrict__ xsrc, const int* __restrict__ srcI,
    const int* __restrict__ dstI, float* __restrict__ agg,
    float* __restrict__ deg, int nE)
{
    int g = blockIdx.x * blockDim.x + threadIdx.x;
    int e = g >> 5;
    if (e >= nE) return;
    int lane = g & 31;
    int s = __ldg(srcI + e);
    int d = __ldg(dstI + e);
    float4 v = ((const float4*)(xsrc + (size_t)s * H))[lane];
    float* p = agg + (size_t)d * H + lane * 4;
    asm volatile("red.global.add.v4.f32 [%0], {%1,%2,%3,%4};"
                 :: "l"(p), "f"(v.x), "f"(v.y), "f"(v.z), "f"(v.w) : "memory");
    if (lane == 0) atomicAdd(deg + d, 1.0f);
}

// ---------------- relu ----------------
__global__ void relu_kernel(float* __restrict__ x, size_t n4)
{
    size_t i = (size_t)blockIdx.x * blockDim.x + threadIdx.x;
    size_t stride = (size_t)gridDim.x * blockDim.x;
    float4* p = (float4*)x;
    for (; i < n4; i += stride) {
        float4 v = p[i];
        v.x = fmaxf(v.x, 0.f); v.y = fmaxf(v.y, 0.f);
        v.z = fmaxf(v.z, 0.f); v.w = fmaxf(v.w, 0.f);
        p[i] = v;
    }
}

// ---------------- final linear ----------------
__global__ void __launch_bounds__(128) final_kernel(
    const float* __restrict__ X, const float* __restrict__ W,
    const float* __restrict__ b, float* __restrict__ out, int M)
{
    __shared__ float Ws[H * 64];
    __shared__ float bs[64];
    for (int i = threadIdx.x; i < H * 64; i += 128) Ws[i] = W[i];
    if (threadIdx.x < 64) bs[threadIdx.x] = b[threadIdx.x];
    __syncthreads();
    int m = blockIdx.x * 128 + threadIdx.x;
    if (m >= M) return;
    float acc[64];
    #pragma unroll
    for (int j = 0; j < 64; j++) acc[j] = bs[j];
    const float* x = X + (size_t)m * H;
    for (int k = 0; k < H; k++) {
        float xv = x[k];
        #pragma unroll
        for (int j = 0; j < 64; j++) acc[j] += xv * Ws[k * 64 + j];
    }
    float* o = out + (size_t)m * 64;
    #pragma unroll
    for (int j = 0; j < 64; j++) o[j] = acc[j];
}

// ---------------- host ----------------
static const int NN[NTYPE]   = {50000,2000,80000,10000,2000,150000,120000,100000,60000,40000};
static const int OFFS[NTYPE] = {0,50000,52000,132000,142000,144000,294000,414000,514000,574000};
static const int R_SRC[NREL] = {0,1,0,2,0,3,0,4,0,5,0,6,6,7,5,6,5,7,4,5,4,3,2,8,2,9};
static const int R_DST[NREL] = {1,0,2,0,3,0,4,0,5,0,6,0,7,6,6,5,7,5,5,4,3,4,8,2,9,2};
static const int R_EI[NREL]  = {10,10,11,11,12,12,13,13,14,14,15,15,16,16,17,17,18,18,19,19,20,20,21,21,22,22};
static const int R_FLIP[NREL]= {0,1,0,1,0,1,0,1,0,1,0,1,0,1,0,1,0,1,0,1,0,1,0,1,0,1};

static inline void launch_gemm(const float* A, const float* W, const float* deg,
                               const float* bias, float* C, int M, int acc)
{
    int ntiles = (M + 127) / 128;
    gemm_mma<<<ntiles, 256, SM_BYTES>>>(A, W, deg, bias, C, M, acc);
}

extern "C" void kernel_launch(void* const* d_in, const int* in_sizes, int n_in,
                              void* d_out, int out_size)
{
    const float* Wl   = (const float*)d_in[23];
    const float* bl   = (const float*)d_in[24];
    const float* Wr   = (const float*)d_in[25];
    const float* linW = (const float*)d_in[26];
    const float* linb = (const float*)d_in[27];

    float *buf0, *buf1, *agg, *deg, *wsum, *bsum;
    cudaGetSymbolAddress((void**)&buf0, g_buf0);
    cudaGetSymbolAddress((void**)&buf1, g_buf1);
    cudaGetSymbolAddress((void**)&agg,  g_agg);
    cudaGetSymbolAddress((void**)&deg,  g_deg);
    cudaGetSymbolAddress((void**)&wsum, g_wsum);
    cudaGetSymbolAddress((void**)&bsum, g_bsum);

    cudaFuncSetAttribute(gemm_mma, cudaFuncAttributeMaxDynamicSharedMemorySize, SM_BYTES);

    wsum_kernel<<<2 * NTYPE, 256>>>(Wr, bl, wsum, bsum);

    const float* cur[NTYPE];
    for (int t = 0; t < NTYPE; t++) cur[t] = (const float*)d_in[t];
    float* bufs[2] = {buf0, buf1};

    for (int layer = 0; layer < 2; layer++) {
        float* outbuf = bufs[layer];

        // self term: out[t] = x[t] @ WrSum[layer,t] + biasSum[layer,t]
        for (int t = 0; t < NTYPE; t++) {
            launch_gemm(cur[t], wsum + ((size_t)layer * NTYPE + t) * H * H, nullptr,
                        bsum + ((size_t)layer * NTYPE + t) * H,
                        outbuf + (size_t)OFFS[t] * H, NN[t], 0);
        }

        // neighbor terms: out[d] += (agg/deg) @ Wl[layer,r]
        for (int r = 0; r < NREL; r++) {
            int s = R_SRC[r], d = R_DST[r], ii = R_EI[r];
            const int* ei = (const int*)d_in[ii];
            int E = in_sizes[ii] / 2;
            const int* srcI = R_FLIP[r] ? ei + E : ei;
            const int* dstI = R_FLIP[r] ? ei : ei + E;
            int nd = NN[d];

            cudaMemsetAsync(agg, 0, (size_t)nd * H * sizeof(float), 0);
            cudaMemsetAsync(deg, 0, (size_t)nd * sizeof(float), 0);

            long threads = (long)E * 32;
            scatter_kernel<<<(unsigned)((threads + 255) / 256), 256>>>(
                cur[s], srcI, dstI, agg, deg, E);

            launch_gemm(agg, Wl + ((size_t)layer * NREL + r) * H * H, deg,
                        nullptr, outbuf + (size_t)OFFS[d] * H, nd, 1);
        }

        relu_kernel<<<4096, 256>>>(outbuf, (size_t)N_TOTAL * H / 4);
        for (int t = 0; t < NTYPE; t++) cur[t] = outbuf + (size_t)OFFS[t] * H;
    }

    final_kernel<<<(NN[0] + 127) / 128, 128>>>(cur[0], linW, linb, (float*)d_out, NN[0]);
}

// round 4
// speedup vs baseline: 1.7328x; 1.3348x over previous
#include <cuda_runtime.h>
#include <cuda_bf16.h>
#include <cstdint>
#include <cstddef>

#define H 128
#define NTYPE 10
#define NREL 26
#define N_TOTAL 614000
#define MAX_DST 150000
#define DEG_TOTAL 1828000

// ---------------- scratch ----------------
__device__ float g_buf0[(size_t)N_TOTAL * H];
__device__ float g_buf1[(size_t)N_TOTAL * H];
__device__ float g_agg[(size_t)MAX_DST * H];
__device__ float g_tmp[(size_t)MAX_DST * H];
__device__ float g_degall[DEG_TOTAL];
__device__ float g_wsum[2 * NTYPE * H * H];
__device__ float g_bsum[2 * NTYPE * H];
// 72 matrices (20 wsum + 52 Wl), each: hi plane [n][k] 16384 bf16, then lo plane
__device__ __nv_bfloat16 g_wbf[72 * 2 * H * H];

__constant__ int c_rel_dst[NREL] = {1,0,2,0,3,0,4,0,5,0,6,0,7,6,6,5,7,5,5,4,3,4,8,2,9,2};

// ---------------- helpers ----------------
__device__ __forceinline__ uint32_t smem_to_u32(const void* p) {
    uint32_t a;
    asm("{ .reg .u64 t; cvta.to.shared.u64 t, %1; cvt.u32.u64 %0, t; }" : "=r"(a) : "l"(p));
    return a;
}

__device__ __forceinline__ void cvt8(const float* v, float scale, uint4& hi, uint4& lo) {
    uint32_t h[4], l[4];
    #pragma unroll
    for (int p = 0; p < 4; p++) {
        float a = v[2*p] * scale, b = v[2*p+1] * scale;
        __nv_bfloat16 ah = __float2bfloat16(a), bh = __float2bfloat16(b);
        float ar = a - __bfloat162float(ah), br = b - __bfloat162float(bh);
        __nv_bfloat16 al = __float2bfloat16(ar), bl2 = __float2bfloat16(br);
        h[p] = (uint32_t)__bfloat16_as_ushort(ah) | ((uint32_t)__bfloat16_as_ushort(bh) << 16);
        l[p] = (uint32_t)__bfloat16_as_ushort(al) | ((uint32_t)__bfloat16_as_ushort(bl2) << 16);
    }
    hi = make_uint4(h[0], h[1], h[2], h[3]);
    lo = make_uint4(l[0], l[1], l[2], l[3]);
}

#define LDMATRIX_X4(r0, r1, r2, r3, addr) \
    asm volatile("ldmatrix.sync.aligned.m8n8.x4.shared.b16 {%0,%1,%2,%3}, [%4];" \
                 : "=r"(r0), "=r"(r1), "=r"(r2), "=r"(r3) : "r"(addr))

#define MMA_BF16(c0, c1, c2, c3, a0, a1, a2, a3, b0, b1) \
    asm volatile("mma.sync.aligned.m16n8k16.row.col.f32.bf16.bf16.f32 " \
                 "{%0,%1,%2,%3}, {%4,%5,%6,%7}, {%8,%9}, {%0,%1,%2,%3};" \
                 : "+f"(c0), "+f"(c1), "+f"(c2), "+f"(c3) \
                 : "r"(a0), "r"(a1), "r"(a2), "r"(a3), "r"(b0), "r"(b1))

// ---------------- bf16 HMMA GEMM v2 ----------------
// 512 threads, 128x128 tile, warp tile 32x32, split-bf16 3-pass, B pre-converted.
#define A_LD 136
#define SM_AH 0
#define SM_AL 34816
#define SM_BH 69632
#define SM_BL 104448
#define SM_BYTES 139264

__global__ void __launch_bounds__(512) gemm_mma(
    const float* __restrict__ A, const __nv_bfloat16* __restrict__ Bbf,
    const float* __restrict__ deg, const float* __restrict__ bias,
    float* __restrict__ C, int M, int accumulate)
{
    extern __shared__ char smem[];
    const uint32_t sb = smem_to_u32(smem);
    const int tid = threadIdx.x, lane = tid & 31, wid = tid >> 5;
    const int m0 = blockIdx.x * 128;

    // ---- stage A: 4 threads per row, each 32 cols ----
    {
        const int r = tid >> 2;
        const int co = (tid & 3) * 32;
        const int m = m0 + r;
        if (m < M) {
            float scale = 1.0f;
            if (deg) scale = 1.0f / fmaxf(deg[m], 1.0f);
            const float4* Ar = (const float4*)(A + (size_t)m * H);
            #pragma unroll
            for (int c = 0; c < 32; c += 8) {
                float4 f0 = Ar[(co + c) >> 2], f1 = Ar[((co + c) >> 2) + 1];
                float v[8] = {f0.x,f0.y,f0.z,f0.w,f1.x,f1.y,f1.z,f1.w};
                uint4 hi, lo;
                cvt8(v, scale, hi, lo);
                *(uint4*)(smem + SM_AH + (size_t)(r * A_LD + co + c) * 2) = hi;
                *(uint4*)(smem + SM_AL + (size_t)(r * A_LD + co + c) * 2) = lo;
            }
        } else {
            uint4 z = make_uint4(0,0,0,0);
            #pragma unroll
            for (int c = 0; c < 32; c += 8) {
                *(uint4*)(smem + SM_AH + (size_t)(r * A_LD + co + c) * 2) = z;
                *(uint4*)(smem + SM_AL + (size_t)(r * A_LD + co + c) * 2) = z;
            }
        }
    }

    // ---- stage B: straight uint4 copies of pre-converted planes ----
    {
        const uint4* srcH = (const uint4*)Bbf;          // hi plane: 2048 uint4
        const uint4* srcL = srcH + 2048;                // lo plane
        #pragma unroll
        for (int it = 0; it < 4; it++) {
            int idx = tid + it * 512;
            int n = idx >> 4, q = idx & 15;
            *(uint4*)(smem + SM_BH + (size_t)n * (A_LD * 2) + q * 16) = srcH[idx];
            *(uint4*)(smem + SM_BL + (size_t)n * (A_LD * 2) + q * 16) = srcL[idx];
        }
    }
    __syncthreads();

    // ---- warp tiling: 4x4 warps, each 32(m) x 32(n) ----
    const int warp_m = (wid >> 2) * 32;
    const int warp_n = (wid & 3) * 32;

    float acc[2][4][4];
    #pragma unroll
    for (int mt = 0; mt < 2; mt++)
        #pragma unroll
        for (int nt = 0; nt < 4; nt++)
            #pragma unroll
            for (int q = 0; q < 4; q++) acc[mt][nt][q] = 0.0f;

    const int lrow = lane & 15;
    const int lcol = (lane >> 4) << 3;

    #pragma unroll
    for (int pass = 0; pass < 3; pass++) {
        const uint32_t abase = sb + (pass == 1 ? SM_AL : SM_AH);
        const uint32_t bbase = sb + (pass == 2 ? SM_BL : SM_BH);
        #pragma unroll
        for (int ks = 0; ks < 8; ks++) {
            const int k0 = ks * 16;
            uint32_t b[8];
            #pragma unroll
            for (int np = 0; np < 2; np++) {
                uint32_t addr = bbase + (uint32_t)(((warp_n + np * 16 + lrow) * A_LD + k0 + lcol) * 2);
                LDMATRIX_X4(b[np*4+0], b[np*4+1], b[np*4+2], b[np*4+3], addr);
            }
            #pragma unroll
            for (int mt = 0; mt < 2; mt++) {
                uint32_t a0, a1, a2, a3;
                uint32_t addr = abase + (uint32_t)(((warp_m + mt * 16 + lrow) * A_LD + k0 + lcol) * 2);
                LDMATRIX_X4(a0, a1, a2, a3, addr);
                MMA_BF16(acc[mt][0][0], acc[mt][0][1], acc[mt][0][2], acc[mt][0][3], a0, a1, a2, a3, b[0], b[2]);
                MMA_BF16(acc[mt][1][0], acc[mt][1][1], acc[mt][1][2], acc[mt][1][3], a0, a1, a2, a3, b[1], b[3]);
                MMA_BF16(acc[mt][2][0], acc[mt][2][1], acc[mt][2][2], acc[mt][2][3], a0, a1, a2, a3, b[4], b[6]);
                MMA_BF16(acc[mt][3][0], acc[mt][3][1], acc[mt][3][2], acc[mt][3][3], a0, a1, a2, a3, b[5], b[7]);
            }
        }
    }

    // ---- epilogue ----
    const int qrow = lane >> 2;
    const int qcol = (lane & 3) * 2;
    #pragma unroll
    for (int mt = 0; mt < 2; mt++) {
        #pragma unroll
        for (int half = 0; half < 2; half++) {
            const int m = m0 + warp_m + mt * 16 + qrow + half * 8;
            if (m < M) {
                float* cp = C + (size_t)m * H;
                #pragma unroll
                for (int nt = 0; nt < 4; nt++) {
                    const int c = warp_n + nt * 8 + qcol;
                    float v0 = acc[mt][nt][half * 2 + 0];
                    float v1 = acc[mt][nt][half * 2 + 1];
                    if (accumulate) {
                        asm volatile("red.global.add.v2.f32 [%0], {%1,%2};"
                                     :: "l"(cp + c), "f"(v0), "f"(v1) : "memory");
                    } else {
                        if (bias) { v0 += bias[c]; v1 += bias[c + 1]; }
                        *(float2*)(cp + c) = make_float2(v0, v1);
                    }
                }
            }
        }
    }
}

// ---------------- Wr / bias reduction ----------------
__global__ void __launch_bounds__(256) wsum_kernel(
    const float* __restrict__ Wr, const float* __restrict__ bl,
    float* __restrict__ wsum, float* __restrict__ bsum)
{
    int layer = blockIdx.x / NTYPE;
    int t = blockIdx.x % NTYPE;
    const float* base = Wr + (size_t)layer * NREL * H * H;
    float* outw = wsum + ((size_t)layer * NTYPE + t) * H * H;
    for (int e = threadIdx.x; e < H * H; e += 256) {
        float a = 0.f;
        #pragma unroll
        for (int r = 0; r < NREL; r++)
            if (c_rel_dst[r] == t) a += base[(size_t)r * H * H + e];
        outw[e] = a;
    }
    if (threadIdx.x < H) {
        float a = 0.f;
        #pragma unroll
        for (int r = 0; r < NREL; r++)
            if (c_rel_dst[r] == t) a += bl[((size_t)layer * NREL + r) * H + threadIdx.x];
        bsum[((size_t)layer * NTYPE + t) * H + threadIdx.x] = a;
    }
}

// ---------------- weight conversion: fp32 [k][n] -> bf16 hi/lo [n][k] planes ----------------
__global__ void __launch_bounds__(256) wcvt_kernel(
    const float* __restrict__ wsum, const float* __restrict__ Wl,
    __nv_bfloat16* __restrict__ wbf)
{
    int m = blockIdx.x;   // 0..71
    const float* src = (m < 20) ? (wsum + (size_t)m * H * H)
                                : (Wl + (size_t)(m - 20) * H * H);
    __nv_bfloat16* hi = wbf + (size_t)m * 2 * H * H;
    __nv_bfloat16* lo = hi + H * H;
    for (int idx = threadIdx.x; idx < H * H; idx += 256) {
        int k = idx >> 7, n = idx & 127;
        float w = src[idx];
        __nv_bfloat16 wh = __float2bfloat16(w);
        float wr = w - __bfloat162float(wh);
        hi[n * H + k] = wh;
        lo[n * H + k] = __float2bfloat16(wr);
    }
}

// ---------------- degree count ----------------
__global__ void __launch_bounds__(256) deg_kernel(
    const int* __restrict__ dstI, float* __restrict__ deg, int nE)
{
    int e = blockIdx.x * blockDim.x + threadIdx.x;
    if (e < nE) atomicAdd(deg + __ldg(dstI + e), 1.0f);
}

// ---------------- edge scatter (dst-side path: into agg, no deg) ----------------
__global__ void __launch_bounds__(256) scatter_kernel(
    const float* __restrict__ xsrc, const int* __restrict__ srcI,
    const int* __restrict__ dstI, float* __restrict__ agg, int nE)
{
    int g = blockIdx.x * blockDim.x + threadIdx.x;
    int e = g >> 5;
    if (e >= nE) return;
    int lane = g & 31;
    int s = __ldg(srcI + e);
    int d = __ldg(dstI + e);
    float4 v = ((const float4*)(xsrc + (size_t)s * H))[lane];
    float* p = agg + (size_t)d * H + lane * 4;
    asm volatile("red.global.add.v4.f32 [%0], {%1,%2,%3,%4};"
                 :: "l"(p), "f"(v.x), "f"(v.y), "f"(v.z), "f"(v.w) : "memory");
}

// ---------------- scaled scatter (src-side path: tmp -> out, *1/deg) ----------------
__global__ void __launch_bounds__(256) scatter_scaled_kernel(
    const float* __restrict__ tmp, const int* __restrict__ srcI,
    const int* __restrict__ dstI, const float* __restrict__ deg,
    float* __restrict__ out, int nE)
{
    int g = blockIdx.x * blockDim.x + threadIdx.x;
    int e = g >> 5;
    if (e >= nE) return;
    int lane = g & 31;
    int s = __ldg(srcI + e);
    int d = __ldg(dstI + e);
    float sc = 1.0f / fmaxf(__ldg(deg + d), 1.0f);
    float4 v = ((const float4*)(tmp + (size_t)s * H))[lane];
    v.x *= sc; v.y *= sc; v.z *= sc; v.w *= sc;
    float* p = out + (size_t)d * H + lane * 4;
    asm volatile("red.global.add.v4.f32 [%0], {%1,%2,%3,%4};"
                 :: "l"(p), "f"(v.x), "f"(v.y), "f"(v.z), "f"(v.w) : "memory");
}

// ---------------- relu ----------------
__global__ void relu_kernel(float* __restrict__ x, size_t n4)
{
    size_t i = (size_t)blockIdx.x * blockDim.x + threadIdx.x;
    size_t stride = (size_t)gridDim.x * blockDim.x;
    float4* p = (float4*)x;
    for (; i < n4; i += stride) {
        float4 v = p[i];
        v.x = fmaxf(v.x, 0.f); v.y = fmaxf(v.y, 0.f);
        v.z = fmaxf(v.z, 0.f); v.w = fmaxf(v.w, 0.f);
        p[i] = v;
    }
}

// ---------------- final linear ----------------
__global__ void __launch_bounds__(128) final_kernel(
    const float* __restrict__ X, const float* __restrict__ W,
    const float* __restrict__ b, float* __restrict__ out, int M)
{
    __shared__ float Ws[H * 64];
    __shared__ float bs[64];
    for (int i = threadIdx.x; i < H * 64; i += 128) Ws[i] = W[i];
    if (threadIdx.x < 64) bs[threadIdx.x] = b[threadIdx.x];
    __syncthreads();
    int m = blockIdx.x * 128 + threadIdx.x;
    if (m >= M) return;
    float acc[64];
    #pragma unroll
    for (int j = 0; j < 64; j++) acc[j] = bs[j];
    const float* x = X + (size_t)m * H;
    for (int k = 0; k < H; k++) {
        float xv = x[k];
        #pragma unroll
        for (int j = 0; j < 64; j++) acc[j] += xv * Ws[k * 64 + j];
    }
    float* o = out + (size_t)m * 64;
    #pragma unroll
    for (int j = 0; j < 64; j++) o[j] = acc[j];
}

// ---------------- host ----------------
static const int NN[NTYPE]   = {50000,2000,80000,10000,2000,150000,120000,100000,60000,40000};
static const int OFFS[NTYPE] = {0,50000,52000,132000,142000,144000,294000,414000,514000,574000};
static const int R_SRC[NREL] = {0,1,0,2,0,3,0,4,0,5,0,6,6,7,5,6,5,7,4,5,4,3,2,8,2,9};
static const int R_DST[NREL] = {1,0,2,0,3,0,4,0,5,0,6,0,7,6,6,5,7,5,5,4,3,4,8,2,9,2};
static const int R_EI[NREL]  = {10,10,11,11,12,12,13,13,14,14,15,15,16,16,17,17,18,18,19,19,20,20,21,21,22,22};
static const int R_FLIP[NREL]= {0,1,0,1,0,1,0,1,0,1,0,1,0,1,0,1,0,1,0,1,0,1,0,1,0,1};

extern "C" void kernel_launch(void* const* d_in, const int* in_sizes, int n_in,
                              void* d_out, int out_size)
{
    const float* Wl   = (const float*)d_in[23];
    const float* linW = (const float*)d_in[26];
    const float* linb = (const float*)d_in[27];
    const float* bl   = (const float*)d_in[24];
    const float* Wr   = (const float*)d_in[25];

    float *buf0, *buf1, *agg, *tmp, *degall, *wsum, *bsum;
    __nv_bfloat16* wbf;
    cudaGetSymbolAddress((void**)&buf0,   g_buf0);
    cudaGetSymbolAddress((void**)&buf1,   g_buf1);
    cudaGetSymbolAddress((void**)&agg,    g_agg);
    cudaGetSymbolAddress((void**)&tmp,    g_tmp);
    cudaGetSymbolAddress((void**)&degall, g_degall);
    cudaGetSymbolAddress((void**)&wsum,   g_wsum);
    cudaGetSymbolAddress((void**)&bsum,   g_bsum);
    cudaGetSymbolAddress((void**)&wbf,    g_wbf);

    cudaFuncSetAttribute(gemm_mma, cudaFuncAttributeMaxDynamicSharedMemorySize, SM_BYTES);

    // degree offsets per relation
    int DEGOFF[NREL];
    {
        int acc = 0;
        for (int r = 0; r < NREL; r++) { DEGOFF[r] = acc; acc += NN[R_DST[r]]; }
    }

    // prep: weights + degrees
    cudaMemsetAsync(degall, 0, (size_t)DEG_TOTAL * sizeof(float), 0);
    wsum_kernel<<<2 * NTYPE, 256>>>(Wr, bl, wsum, bsum);
    wcvt_kernel<<<72, 256>>>(wsum, Wl, wbf);
    for (int r = 0; r < NREL; r++) {
        int ii = R_EI[r];
        const int* ei = (const int*)d_in[ii];
        int E = in_sizes[ii] / 2;
        const int* dstI = R_FLIP[r] ? ei : ei + E;
        deg_kernel<<<(E + 255) / 256, 256>>>(dstI, degall + DEGOFF[r], E);
    }

    const float* cur[NTYPE];
    for (int t = 0; t < NTYPE; t++) cur[t] = (const float*)d_in[t];
    float* bufs[2] = {buf0, buf1};

    for (int layer = 0; layer < 2; layer++) {
        float* outbuf = bufs[layer];

        // self term: out[t] = x[t] @ WrSum + biasSum (plain store)
        for (int t = 0; t < NTYPE; t++) {
            gemm_mma<<<(NN[t] + 127) / 128, 512, SM_BYTES>>>(
                cur[t], wbf + (size_t)(layer * NTYPE + t) * 2 * H * H,
                nullptr, bsum + ((size_t)layer * NTYPE + t) * H,
                outbuf + (size_t)OFFS[t] * H, NN[t], 0);
        }

        // neighbor terms
        for (int r = 0; r < NREL; r++) {
            int s = R_SRC[r], d = R_DST[r], ii = R_EI[r];
            const int* ei = (const int*)d_in[ii];
            int E = in_sizes[ii] / 2;
            const int* srcI = R_FLIP[r] ? ei + E : ei;
            const int* dstI = R_FLIP[r] ? ei : ei + E;
            int nd = NN[d];
            const __nv_bfloat16* wmat = wbf + (size_t)(20 + layer * NREL + r) * 2 * H * H;
            const float* deg = degall + DEGOFF[r];
            long warpthreads = (long)E * 32;
            unsigned sgrid = (unsigned)((warpthreads + 255) / 256);

            if (NN[s] < nd) {
                // src-side: transform then scaled-scatter directly into out
                gemm_mma<<<(NN[s] + 127) / 128, 512, SM_BYTES>>>(
                    cur[s], wmat, nullptr, nullptr, tmp, NN[s], 0);
                scatter_scaled_kernel<<<sgrid, 256>>>(tmp, srcI, dstI, deg,
                                                      outbuf + (size_t)OFFS[d] * H, E);
            } else {
                // dst-side: scatter into agg, then GEMM with deg row-scale, red into out
                cudaMemsetAsync(agg, 0, (size_t)nd * H * sizeof(float), 0);
                scatter_kernel<<<sgrid, 256>>>(cur[s], srcI, dstI, agg, E);
                gemm_mma<<<(nd + 127) / 128, 512, SM_BYTES>>>(
                    agg, wmat, deg, nullptr,
                    outbuf + (size_t)OFFS[d] * H, nd, 1);
            }
        }

        relu_kernel<<<4096, 256>>>(outbuf, (size_t)N_TOTAL * H / 4);
        for (int t = 0; t < NTYPE; t++) cur[t] = outbuf + (size_t)OFFS[t] * H;
    }

    final_kernel<<<(NN[0] + 127) / 128, 128>>>(cur[0], linW, linb, (float*)d_out, NN[0]);
}

// round 5
// speedup vs baseline: 1.8758x; 1.0825x over previous
#include <cuda_runtime.h>
#include <cuda_bf16.h>
#include <cstdint>
#include <cstddef>

#define H 128
#define NTYPE 10
#define NREL 26
#define N_TOTAL 614000
#define MAX_DST 150000
#define DEG_TOTAL 1828000
#define EDGE_TOTAL (26 * 300000)

// ---------------- scratch ----------------
__device__ float g_buf0[(size_t)N_TOTAL * H];
__device__ float g_buf1[(size_t)N_TOTAL * H];
__device__ float g_agg[(size_t)MAX_DST * H];
__device__ float g_tmp[(size_t)MAX_DST * H];
__device__ int   g_head[DEG_TOTAL];
__device__ int   g_next[EDGE_TOTAL];
__device__ float g_wsum[2 * NTYPE * H * H];
__device__ float g_bsum[2 * NTYPE * H];
__device__ __nv_bfloat16 g_wbf[72 * 2 * H * H];

__constant__ int c_rel_dst[NREL] = {1,0,2,0,3,0,4,0,5,0,6,0,7,6,6,5,7,5,5,4,3,4,8,2,9,2};

// ---------------- helpers ----------------
__device__ __forceinline__ uint32_t smem_to_u32(const void* p) {
    uint32_t a;
    asm("{ .reg .u64 t; cvta.to.shared.u64 t, %1; cvt.u32.u64 %0, t; }" : "=r"(a) : "l"(p));
    return a;
}

__device__ __forceinline__ void cvt8(const float* v, uint4& hi, uint4& lo) {
    uint32_t h[4], l[4];
    #pragma unroll
    for (int p = 0; p < 4; p++) {
        float a = v[2*p], b = v[2*p+1];
        __nv_bfloat16 ah = __float2bfloat16(a), bh = __float2bfloat16(b);
        float ar = a - __bfloat162float(ah), br = b - __bfloat162float(bh);
        __nv_bfloat16 al = __float2bfloat16(ar), bl2 = __float2bfloat16(br);
        h[p] = (uint32_t)__bfloat16_as_ushort(ah) | ((uint32_t)__bfloat16_as_ushort(bh) << 16);
        l[p] = (uint32_t)__bfloat16_as_ushort(al) | ((uint32_t)__bfloat16_as_ushort(bl2) << 16);
    }
    hi = make_uint4(h[0], h[1], h[2], h[3]);
    lo = make_uint4(l[0], l[1], l[2], l[3]);
}

#define LDMATRIX_X4(r0, r1, r2, r3, addr) \
    asm volatile("ldmatrix.sync.aligned.m8n8.x4.shared.b16 {%0,%1,%2,%3}, [%4];" \
                 : "=r"(r0), "=r"(r1), "=r"(r2), "=r"(r3) : "r"(addr))

#define MMA_BF16(c0, c1, c2, c3, a0, a1, a2, a3, b0, b1) \
    asm volatile("mma.sync.aligned.m16n8k16.row.col.f32.bf16.bf16.f32 " \
                 "{%0,%1,%2,%3}, {%4,%5,%6,%7}, {%8,%9}, {%0,%1,%2,%3};" \
                 : "+f"(c0), "+f"(c1), "+f"(c2), "+f"(c3) \
                 : "r"(a0), "r"(a1), "r"(a2), "r"(a3), "r"(b0), "r"(b1))

// ---------------- bf16 HMMA GEMM ----------------
#define A_LD 136
#define SM_AH 0
#define SM_AL 34816
#define SM_BH 69632
#define SM_BL 104448
#define SM_BYTES 139264

__global__ void __launch_bounds__(512) gemm_mma(
    const float* __restrict__ A, const __nv_bfloat16* __restrict__ Bbf,
    const float* __restrict__ bias, float* __restrict__ C,
    int M, int accumulate, int doRelu)
{
    extern __shared__ char smem[];
    const uint32_t sb = smem_to_u32(smem);
    const int tid = threadIdx.x, lane = tid & 31, wid = tid >> 5;
    const int m0 = blockIdx.x * 128;

    // ---- stage A: 4 threads per row, each 32 cols ----
    {
        const int r = tid >> 2;
        const int co = (tid & 3) * 32;
        const int m = m0 + r;
        if (m < M) {
            const float4* Ar = (const float4*)(A + (size_t)m * H);
            #pragma unroll
            for (int c = 0; c < 32; c += 8) {
                float4 f0 = Ar[(co + c) >> 2], f1 = Ar[((co + c) >> 2) + 1];
                float v[8] = {f0.x,f0.y,f0.z,f0.w,f1.x,f1.y,f1.z,f1.w};
                if (doRelu) {
                    #pragma unroll
                    for (int j = 0; j < 8; j++) v[j] = fmaxf(v[j], 0.f);
                }
                uint4 hi, lo;
                cvt8(v, hi, lo);
                *(uint4*)(smem + SM_AH + (size_t)(r * A_LD + co + c) * 2) = hi;
                *(uint4*)(smem + SM_AL + (size_t)(r * A_LD + co + c) * 2) = lo;
            }
        } else {
            uint4 z = make_uint4(0,0,0,0);
            #pragma unroll
            for (int c = 0; c < 32; c += 8) {
                *(uint4*)(smem + SM_AH + (size_t)(r * A_LD + co + c) * 2) = z;
                *(uint4*)(smem + SM_AL + (size_t)(r * A_LD + co + c) * 2) = z;
            }
        }
    }

    // ---- stage B ----
    {
        const uint4* srcH = (const uint4*)Bbf;
        const uint4* srcL = srcH + 2048;
        #pragma unroll
        for (int it = 0; it < 4; it++) {
            int idx = tid + it * 512;
            int n = idx >> 4, q = idx & 15;
            *(uint4*)(smem + SM_BH + (size_t)n * (A_LD * 2) + q * 16) = srcH[idx];
            *(uint4*)(smem + SM_BL + (size_t)n * (A_LD * 2) + q * 16) = srcL[idx];
        }
    }
    __syncthreads();

    const int warp_m = (wid >> 2) * 32;
    const int warp_n = (wid & 3) * 32;

    float acc[2][4][4];
    #pragma unroll
    for (int mt = 0; mt < 2; mt++)
        #pragma unroll
        for (int nt = 0; nt < 4; nt++)
            #pragma unroll
            for (int q = 0; q < 4; q++) acc[mt][nt][q] = 0.0f;

    const int lrow = lane & 15;
    const int lcol = (lane >> 4) << 3;

    #pragma unroll
    for (int pass = 0; pass < 3; pass++) {
        const uint32_t abase = sb + (pass == 1 ? SM_AL : SM_AH);
        const uint32_t bbase = sb + (pass == 2 ? SM_BL : SM_BH);
        #pragma unroll
        for (int ks = 0; ks < 8; ks++) {
            const int k0 = ks * 16;
            uint32_t b[8];
            #pragma unroll
            for (int np = 0; np < 2; np++) {
                uint32_t addr = bbase + (uint32_t)(((warp_n + np * 16 + lrow) * A_LD + k0 + lcol) * 2);
                LDMATRIX_X4(b[np*4+0], b[np*4+1], b[np*4+2], b[np*4+3], addr);
            }
            #pragma unroll
            for (int mt = 0; mt < 2; mt++) {
                uint32_t a0, a1, a2, a3;
                uint32_t addr = abase + (uint32_t)(((warp_m + mt * 16 + lrow) * A_LD + k0 + lcol) * 2);
                LDMATRIX_X4(a0, a1, a2, a3, addr);
                MMA_BF16(acc[mt][0][0], acc[mt][0][1], acc[mt][0][2], acc[mt][0][3], a0, a1, a2, a3, b[0], b[2]);
                MMA_BF16(acc[mt][1][0], acc[mt][1][1], acc[mt][1][2], acc[mt][1][3], a0, a1, a2, a3, b[1], b[3]);
                MMA_BF16(acc[mt][2][0], acc[mt][2][1], acc[mt][2][2], acc[mt][2][3], a0, a1, a2, a3, b[4], b[6]);
                MMA_BF16(acc[mt][3][0], acc[mt][3][1], acc[mt][3][2], acc[mt][3][3], a0, a1, a2, a3, b[5], b[7]);
            }
        }
    }

    const int qrow = lane >> 2;
    const int qcol = (lane & 3) * 2;
    #pragma unroll
    for (int mt = 0; mt < 2; mt++) {
        #pragma unroll
        for (int half = 0; half < 2; half++) {
            const int m = m0 + warp_m + mt * 16 + qrow + half * 8;
            if (m < M) {
                float* cp = C + (size_t)m * H;
                #pragma unroll
                for (int nt = 0; nt < 4; nt++) {
                    const int c = warp_n + nt * 8 + qcol;
                    float v0 = acc[mt][nt][half * 2 + 0];
                    float v1 = acc[mt][nt][half * 2 + 1];
                    if (accumulate) {
                        asm volatile("red.global.add.v2.f32 [%0], {%1,%2};"
                                     :: "l"(cp + c), "f"(v0), "f"(v1) : "memory");
                    } else {
                        if (bias) { v0 += bias[c]; v1 += bias[c + 1]; }
                        *(float2*)(cp + c) = make_float2(v0, v1);
                    }
                }
            }
        }
    }
}

// ---------------- Wr / bias reduction ----------------
__global__ void __launch_bounds__(256) wsum_kernel(
    const float* __restrict__ Wr, const float* __restrict__ bl,
    float* __restrict__ wsum, float* __restrict__ bsum)
{
    int layer = blockIdx.x / NTYPE;
    int t = blockIdx.x % NTYPE;
    const float* base = Wr + (size_t)layer * NREL * H * H;
    float* outw = wsum + ((size_t)layer * NTYPE + t) * H * H;
    for (int e = threadIdx.x; e < H * H; e += 256) {
        float a = 0.f;
        #pragma unroll
        for (int r = 0; r < NREL; r++)
            if (c_rel_dst[r] == t) a += base[(size_t)r * H * H + e];
        outw[e] = a;
    }
    if (threadIdx.x < H) {
        float a = 0.f;
        #pragma unroll
        for (int r = 0; r < NREL; r++)
            if (c_rel_dst[r] == t) a += bl[((size_t)layer * NREL + r) * H + threadIdx.x];
        bsum[((size_t)layer * NTYPE + t) * H + threadIdx.x] = a;
    }
}

// ---------------- weight conversion ----------------
__global__ void __launch_bounds__(256) wcvt_kernel(
    const float* __restrict__ wsum, const float* __restrict__ Wl,
    __nv_bfloat16* __restrict__ wbf)
{
    int m = blockIdx.x;   // 0..71
    const float* src = (m < 20) ? (wsum + (size_t)m * H * H)
                                : (Wl + (size_t)(m - 20) * H * H);
    __nv_bfloat16* hi = wbf + (size_t)m * 2 * H * H;
    __nv_bfloat16* lo = hi + H * H;
    for (int idx = threadIdx.x; idx < H * H; idx += 256) {
        int k = idx >> 7, n = idx & 127;
        float w = src[idx];
        __nv_bfloat16 wh = __float2bfloat16(w);
        float wr = w - __bfloat162float(wh);
        hi[n * H + k] = wh;
        lo[n * H + k] = __float2bfloat16(wr);
    }
}

// ---------------- chain build: next[e] = atomicExch(head[dst[e]], e) ----------------
__global__ void __launch_bounds__(256) build_chain_kernel(
    const int* __restrict__ dstI, int* __restrict__ head,
    int* __restrict__ next, int nE)
{
    int e = blockIdx.x * blockDim.x + threadIdx.x;
    if (e < nE) next[e] = atomicExch(head + __ldg(dstI + e), e);
}

// ---------------- chain gather: per-node mean of src rows ----------------
// doRed=0: out[node] = mean (plain store).  doRed=1: out[node] += mean (red.v4).
__global__ void __launch_bounds__(256) gather_kernel(
    const float* __restrict__ x, const int* __restrict__ srcI,
    const int* __restrict__ head, const int* __restrict__ next,
    float* __restrict__ out, int nNodes, int doRelu, int doRed)
{
    int warp = blockIdx.x * (blockDim.x >> 5) + (threadIdx.x >> 5);
    if (warp >= nNodes) return;
    const int lane = threadIdx.x & 31;
    int e = __ldg(head + warp);
    float4 acc = make_float4(0.f, 0.f, 0.f, 0.f);
    float cnt = 0.f;
    while (e >= 0) {
        int s  = __ldg(srcI + e);   // uniform across warp -> broadcast
        int nx = __ldg(next + e);
        float4 v = __ldg(((const float4*)(x + (size_t)s * H)) + lane);
        if (doRelu) {
            v.x = fmaxf(v.x, 0.f); v.y = fmaxf(v.y, 0.f);
            v.z = fmaxf(v.z, 0.f); v.w = fmaxf(v.w, 0.f);
        }
        acc.x += v.x; acc.y += v.y; acc.z += v.z; acc.w += v.w;
        cnt += 1.f;
        e = nx;
    }
    float sc = 1.0f / fmaxf(cnt, 1.0f);
    acc.x *= sc; acc.y *= sc; acc.z *= sc; acc.w *= sc;
    float* p = out + (size_t)warp * H + lane * 4;
    if (doRed) {
        asm volatile("red.global.add.v4.f32 [%0], {%1,%2,%3,%4};"
                     :: "l"(p), "f"(acc.x), "f"(acc.y), "f"(acc.z), "f"(acc.w) : "memory");
    } else {
        *(float4*)p = acc;
    }
}

// ---------------- final linear (with fused relu on input) ----------------
__global__ void __launch_bounds__(128) final_kernel(
    const float* __restrict__ X, const float* __restrict__ W,
    const float* __restrict__ b, float* __restrict__ out, int M)
{
    __shared__ float Ws[H * 64];
    __shared__ float bs[64];
    for (int i = threadIdx.x; i < H * 64; i += 128) Ws[i] = W[i];
    if (threadIdx.x < 64) bs[threadIdx.x] = b[threadIdx.x];
    __syncthreads();
    int m = blockIdx.x * 128 + threadIdx.x;
    if (m >= M) return;
    float acc[64];
    #pragma unroll
    for (int j = 0; j < 64; j++) acc[j] = bs[j];
    const float* x = X + (size_t)m * H;
    for (int k = 0; k < H; k++) {
        float xv = fmaxf(x[k], 0.f);
        #pragma unroll
        for (int j = 0; j < 64; j++) acc[j] += xv * Ws[k * 64 + j];
    }
    float* o = out + (size_t)m * 64;
    #pragma unroll
    for (int j = 0; j < 64; j++) o[j] = acc[j];
}

// ---------------- host ----------------
static const int NN[NTYPE]   = {50000,2000,80000,10000,2000,150000,120000,100000,60000,40000};
static const int OFFS[NTYPE] = {0,50000,52000,132000,142000,144000,294000,414000,514000,574000};
static const int R_SRC[NREL] = {0,1,0,2,0,3,0,4,0,5,0,6,6,7,5,6,5,7,4,5,4,3,2,8,2,9};
static const int R_DST[NREL] = {1,0,2,0,3,0,4,0,5,0,6,0,7,6,6,5,7,5,5,4,3,4,8,2,9,2};
static const int R_EI[NREL]  = {10,10,11,11,12,12,13,13,14,14,15,15,16,16,17,17,18,18,19,19,20,20,21,21,22,22};
static const int R_FLIP[NREL]= {0,1,0,1,0,1,0,1,0,1,0,1,0,1,0,1,0,1,0,1,0,1,0,1,0,1};

extern "C" void kernel_launch(void* const* d_in, const int* in_sizes, int n_in,
                              void* d_out, int out_size)
{
    const float* Wl   = (const float*)d_in[23];
    const float* bl   = (const float*)d_in[24];
    const float* Wr   = (const float*)d_in[25];
    const float* linW = (const float*)d_in[26];
    const float* linb = (const float*)d_in[27];

    float *buf0, *buf1, *agg, *tmp, *wsum, *bsum;
    int *head, *nxt;
    __nv_bfloat16* wbf;
    cudaGetSymbolAddress((void**)&buf0, g_buf0);
    cudaGetSymbolAddress((void**)&buf1, g_buf1);
    cudaGetSymbolAddress((void**)&agg,  g_agg);
    cudaGetSymbolAddress((void**)&tmp,  g_tmp);
    cudaGetSymbolAddress((void**)&head, g_head);
    cudaGetSymbolAddress((void**)&nxt,  g_next);
    cudaGetSymbolAddress((void**)&wsum, g_wsum);
    cudaGetSymbolAddress((void**)&bsum, g_bsum);
    cudaGetSymbolAddress((void**)&wbf,  g_wbf);

    cudaFuncSetAttribute(gemm_mma, cudaFuncAttributeMaxDynamicSharedMemorySize, SM_BYTES);

    // per-relation offsets
    int DEGOFF[NREL], EOFF[NREL];
    {
        int a = 0, b2 = 0;
        for (int r = 0; r < NREL; r++) {
            DEGOFF[r] = a; a += NN[R_DST[r]];
            EOFF[r] = b2; b2 += in_sizes[R_EI[r]] / 2;
        }
    }

    // ---- prep: weights + chains ----
    wsum_kernel<<<2 * NTYPE, 256>>>(Wr, bl, wsum, bsum);
    wcvt_kernel<<<72, 256>>>(wsum, Wl, wbf);
    cudaMemsetAsync(head, 0xFF, (size_t)DEG_TOTAL * sizeof(int), 0);
    for (int r = 0; r < NREL; r++) {
        int ii = R_EI[r];
        const int* ei = (const int*)d_in[ii];
        int E = in_sizes[ii] / 2;
        const int* dstI = R_FLIP[r] ? ei : ei + E;
        build_chain_kernel<<<(E + 255) / 256, 256>>>(dstI, head + DEGOFF[r], nxt + EOFF[r], E);
    }

    const float* cur[NTYPE];
    for (int t = 0; t < NTYPE; t++) cur[t] = (const float*)d_in[t];
    float* bufs[2] = {buf0, buf1};

    for (int layer = 0; layer < 2; layer++) {
        float* outbuf = bufs[layer];
        const int lrelu = (layer == 1);   // bufs hold pre-relu values

        // self term
        for (int t = 0; t < NTYPE; t++) {
            gemm_mma<<<(NN[t] + 127) / 128, 512, SM_BYTES>>>(
                cur[t], wbf + (size_t)(layer * NTYPE + t) * 2 * H * H,
                bsum + ((size_t)layer * NTYPE + t) * H,
                outbuf + (size_t)OFFS[t] * H, NN[t], 0, lrelu);
        }

        // neighbor terms
        for (int r = 0; r < NREL; r++) {
            int s = R_SRC[r], d = R_DST[r], ii = R_EI[r];
            const int* ei = (const int*)d_in[ii];
            int E = in_sizes[ii] / 2;
            const int* srcI = R_FLIP[r] ? ei + E : ei;
            int nd = NN[d];
            const __nv_bfloat16* wmat = wbf + (size_t)(20 + layer * NREL + r) * 2 * H * H;
            unsigned ggrid = (unsigned)((nd + 7) / 8);

            if (NN[s] < nd) {
                // src-side: transform first, then mean-gather + red into out
                gemm_mma<<<(NN[s] + 127) / 128, 512, SM_BYTES>>>(
                    cur[s], wmat, nullptr, tmp, NN[s], 0, lrelu);
                gather_kernel<<<ggrid, 256>>>(tmp, srcI, head + DEGOFF[r], nxt + EOFF[r],
                                              outbuf + (size_t)OFFS[d] * H, nd, 0, 1);
            } else {
                // dst-side: mean-gather into agg (plain store), then GEMM red into out
                gather_kernel<<<ggrid, 256>>>(cur[s], srcI, head + DEGOFF[r], nxt + EOFF[r],
                                              agg, nd, lrelu, 0);
                gemm_mma<<<(nd + 127) / 128, 512, SM_BYTES>>>(
                    agg, wmat, nullptr, outbuf + (size_t)OFFS[d] * H, nd, 1, 0);
            }
        }

        for (int t = 0; t < NTYPE; t++) cur[t] = outbuf + (size_t)OFFS[t] * H;
    }

    final_kernel<<<(NN[0] + 127) / 128, 128>>>(cur[0], linW, linb, (float*)d_out, NN[0]);
}

// round 6
// speedup vs baseline: 3.7674x; 2.0084x over previous
#include <cuda_runtime.h>
#include <cuda_bf16.h>
#include <cstdint>
#include <cstddef>

#define H 128
#define NTYPE 10
#define NREL 26
#define N_TOTAL 614000
#define MAX_DST 150000
#define DEG_TOTAL 1828000
#define EDGE_TOTAL (26 * 300000)

// ---------------- scratch ----------------
__device__ float g_buf0[(size_t)N_TOTAL * H];
__device__ float g_buf1[(size_t)N_TOTAL * H];
__device__ float g_agg[(size_t)MAX_DST * H];
__device__ float g_tmp[(size_t)MAX_DST * H];
__device__ int   g_head[DEG_TOTAL];
__device__ int   g_next[EDGE_TOTAL];
__device__ float g_wsum[2 * NTYPE * H * H];
__device__ float g_bsum[2 * NTYPE * H];
__device__ __nv_bfloat16 g_wbf[72 * 2 * H * H];

__constant__ int c_rel_dst[NREL] = {1,0,2,0,3,0,4,0,5,0,6,0,7,6,6,5,7,5,5,4,3,4,8,2,9,2};

// ---------------- helpers ----------------
__device__ __forceinline__ uint32_t smem_to_u32(const void* p) {
    uint32_t a;
    asm("{ .reg .u64 t; cvta.to.shared.u64 t, %1; cvt.u32.u64 %0, t; }" : "=r"(a) : "l"(p));
    return a;
}

__device__ __forceinline__ void cvt8(const float* v, uint4& hi, uint4& lo) {
    uint32_t h[4], l[4];
    #pragma unroll
    for (int p = 0; p < 4; p++) {
        float a = v[2*p], b = v[2*p+1];
        __nv_bfloat16 ah = __float2bfloat16(a), bh = __float2bfloat16(b);
        float ar = a - __bfloat162float(ah), br = b - __bfloat162float(bh);
        __nv_bfloat16 al = __float2bfloat16(ar), bl2 = __float2bfloat16(br);
        h[p] = (uint32_t)__bfloat16_as_ushort(ah) | ((uint32_t)__bfloat16_as_ushort(bh) << 16);
        l[p] = (uint32_t)__bfloat16_as_ushort(al) | ((uint32_t)__bfloat16_as_ushort(bl2) << 16);
    }
    hi = make_uint4(h[0], h[1], h[2], h[3]);
    lo = make_uint4(l[0], l[1], l[2], l[3]);
}

#define LDMATRIX_X4(r0, r1, r2, r3, addr) \
    asm volatile("ldmatrix.sync.aligned.m8n8.x4.shared.b16 {%0,%1,%2,%3}, [%4];" \
                 : "=r"(r0), "=r"(r1), "=r"(r2), "=r"(r3) : "r"(addr))

#define MMA_BF16(c0, c1, c2, c3, a0, a1, a2, a3, b0, b1) \
    asm volatile("mma.sync.aligned.m16n8k16.row.col.f32.bf16.bf16.f32 " \
                 "{%0,%1,%2,%3}, {%4,%5,%6,%7}, {%8,%9}, {%0,%1,%2,%3};" \
                 : "+f"(c0), "+f"(c1), "+f"(c2), "+f"(c3) \
                 : "r"(a0), "r"(a1), "r"(a2), "r"(a3), "r"(b0), "r"(b1))

// ---------------- bf16 HMMA GEMM ----------------
#define A_LD 136
#define SM_AH 0
#define SM_AL 34816
#define SM_BH 69632
#define SM_BL 104448
#define SM_BYTES 139264

__global__ void __launch_bounds__(512) gemm_mma(
    const float* __restrict__ A, const __nv_bfloat16* __restrict__ Bbf,
    const float* __restrict__ bias, float* __restrict__ C,
    int M, int accumulate, int doRelu)
{
    extern __shared__ char smem[];
    const uint32_t sb = smem_to_u32(smem);
    const int tid = threadIdx.x, lane = tid & 31, wid = tid >> 5;
    const int m0 = blockIdx.x * 128;

    // ---- stage A ----
    {
        const int r = tid >> 2;
        const int co = (tid & 3) * 32;
        const int m = m0 + r;
        if (m < M) {
            const float4* Ar = (const float4*)(A + (size_t)m * H);
            #pragma unroll
            for (int c = 0; c < 32; c += 8) {
                float4 f0 = Ar[(co + c) >> 2], f1 = Ar[((co + c) >> 2) + 1];
                float v[8] = {f0.x,f0.y,f0.z,f0.w,f1.x,f1.y,f1.z,f1.w};
                if (doRelu) {
                    #pragma unroll
                    for (int j = 0; j < 8; j++) v[j] = fmaxf(v[j], 0.f);
                }
                uint4 hi, lo;
                cvt8(v, hi, lo);
                *(uint4*)(smem + SM_AH + (size_t)(r * A_LD + co + c) * 2) = hi;
                *(uint4*)(smem + SM_AL + (size_t)(r * A_LD + co + c) * 2) = lo;
            }
        } else {
            uint4 z = make_uint4(0,0,0,0);
            #pragma unroll
            for (int c = 0; c < 32; c += 8) {
                *(uint4*)(smem + SM_AH + (size_t)(r * A_LD + co + c) * 2) = z;
                *(uint4*)(smem + SM_AL + (size_t)(r * A_LD + co + c) * 2) = z;
            }
        }
    }

    // ---- stage B ----
    {
        const uint4* srcH = (const uint4*)Bbf;
        const uint4* srcL = srcH + 2048;
        #pragma unroll
        for (int it = 0; it < 4; it++) {
            int idx = tid + it * 512;
            int n = idx >> 4, q = idx & 15;
            *(uint4*)(smem + SM_BH + (size_t)n * (A_LD * 2) + q * 16) = srcH[idx];
            *(uint4*)(smem + SM_BL + (size_t)n * (A_LD * 2) + q * 16) = srcL[idx];
        }
    }
    __syncthreads();

    const int warp_m = (wid >> 2) * 32;
    const int warp_n = (wid & 3) * 32;

    float acc[2][4][4];
    #pragma unroll
    for (int mt = 0; mt < 2; mt++)
        #pragma unroll
        for (int nt = 0; nt < 4; nt++)
            #pragma unroll
            for (int q = 0; q < 4; q++) acc[mt][nt][q] = 0.0f;

    const int lrow = lane & 15;
    const int lcol = (lane >> 4) << 3;

    #pragma unroll
    for (int pass = 0; pass < 3; pass++) {
        const uint32_t abase = sb + (pass == 1 ? SM_AL : SM_AH);
        const uint32_t bbase = sb + (pass == 2 ? SM_BL : SM_BH);
        #pragma unroll
        for (int ks = 0; ks < 8; ks++) {
            const int k0 = ks * 16;
            uint32_t b[8];
            #pragma unroll
            for (int np = 0; np < 2; np++) {
                uint32_t addr = bbase + (uint32_t)(((warp_n + np * 16 + lrow) * A_LD + k0 + lcol) * 2);
                LDMATRIX_X4(b[np*4+0], b[np*4+1], b[np*4+2], b[np*4+3], addr);
            }
            #pragma unroll
            for (int mt = 0; mt < 2; mt++) {
                uint32_t a0, a1, a2, a3;
                uint32_t addr = abase + (uint32_t)(((warp_m + mt * 16 + lrow) * A_LD + k0 + lcol) * 2);
                LDMATRIX_X4(a0, a1, a2, a3, addr);
                MMA_BF16(acc[mt][0][0], acc[mt][0][1], acc[mt][0][2], acc[mt][0][3], a0, a1, a2, a3, b[0], b[2]);
                MMA_BF16(acc[mt][1][0], acc[mt][1][1], acc[mt][1][2], acc[mt][1][3], a0, a1, a2, a3, b[1], b[3]);
                MMA_BF16(acc[mt][2][0], acc[mt][2][1], acc[mt][2][2], acc[mt][2][3], a0, a1, a2, a3, b[4], b[6]);
                MMA_BF16(acc[mt][3][0], acc[mt][3][1], acc[mt][3][2], acc[mt][3][3], a0, a1, a2, a3, b[5], b[7]);
            }
        }
    }

    const int qrow = lane >> 2;
    const int qcol = (lane & 3) * 2;
    #pragma unroll
    for (int mt = 0; mt < 2; mt++) {
        #pragma unroll
        for (int half = 0; half < 2; half++) {
            const int m = m0 + warp_m + mt * 16 + qrow + half * 8;
            if (m < M) {
                float* cp = C + (size_t)m * H;
                #pragma unroll
                for (int nt = 0; nt < 4; nt++) {
                    const int c = warp_n + nt * 8 + qcol;
                    float v0 = acc[mt][nt][half * 2 + 0];
                    float v1 = acc[mt][nt][half * 2 + 1];
                    if (accumulate) {
                        asm volatile("red.global.add.v2.f32 [%0], {%1,%2};"
                                     :: "l"(cp + c), "f"(v0), "f"(v1) : "memory");
                    } else {
                        if (bias) { v0 += bias[c]; v1 += bias[c + 1]; }
                        *(float2*)(cp + c) = make_float2(v0, v1);
                    }
                }
            }
        }
    }
}

// ---------------- Wr / bias reduction ----------------
__global__ void __launch_bounds__(256) wsum_kernel(
    const float* __restrict__ Wr, const float* __restrict__ bl,
    float* __restrict__ wsum, float* __restrict__ bsum)
{
    int layer = blockIdx.x / NTYPE;
    int t = blockIdx.x % NTYPE;
    const float* base = Wr + (size_t)layer * NREL * H * H;
    float* outw = wsum + ((size_t)layer * NTYPE + t) * H * H;
    for (int e = threadIdx.x; e < H * H; e += 256) {
        float a = 0.f;
        #pragma unroll
        for (int r = 0; r < NREL; r++)
            if (c_rel_dst[r] == t) a += base[(size_t)r * H * H + e];
        outw[e] = a;
    }
    if (threadIdx.x < H) {
        float a = 0.f;
        #pragma unroll
        for (int r = 0; r < NREL; r++)
            if (c_rel_dst[r] == t) a += bl[((size_t)layer * NREL + r) * H + threadIdx.x];
        bsum[((size_t)layer * NTYPE + t) * H + threadIdx.x] = a;
    }
}

// ---------------- weight conversion ----------------
__global__ void __launch_bounds__(256) wcvt_kernel(
    const float* __restrict__ wsum, const float* __restrict__ Wl,
    __nv_bfloat16* __restrict__ wbf)
{
    int m = blockIdx.x;   // 0..71
    const float* src = (m < 20) ? (wsum + (size_t)m * H * H)
                                : (Wl + (size_t)(m - 20) * H * H);
    __nv_bfloat16* hi = wbf + (size_t)m * 2 * H * H;
    __nv_bfloat16* lo = hi + H * H;
    for (int idx = threadIdx.x; idx < H * H; idx += 256) {
        int k = idx >> 7, n = idx & 127;
        float w = src[idx];
        __nv_bfloat16 wh = __float2bfloat16(w);
        float wr = w - __bfloat162float(wh);
        hi[n * H + k] = wh;
        lo[n * H + k] = __float2bfloat16(wr);
    }
}

// ---------------- chain build ----------------
__global__ void __launch_bounds__(256) build_chain_kernel(
    const int* __restrict__ dstI, int* __restrict__ head,
    int* __restrict__ next, int nE)
{
    int e = blockIdx.x * blockDim.x + threadIdx.x;
    if (e < nE) next[e] = atomicExch(head + __ldg(dstI + e), e);
}

// ---------------- chain gather ----------------
__global__ void __launch_bounds__(256) gather_kernel(
    const float* __restrict__ x, const int* __restrict__ srcI,
    const int* __restrict__ head, const int* __restrict__ next,
    float* __restrict__ out, int nNodes, int doRelu, int doRed)
{
    int warp = blockIdx.x * (blockDim.x >> 5) + (threadIdx.x >> 5);
    if (warp >= nNodes) return;
    const int lane = threadIdx.x & 31;
    int e = __ldg(head + warp);
    float4 acc = make_float4(0.f, 0.f, 0.f, 0.f);
    float cnt = 0.f;
    while (e >= 0) {
        int s  = __ldg(srcI + e);
        int nx = __ldg(next + e);
        float4 v = __ldg(((const float4*)(x + (size_t)s * H)) + lane);
        if (doRelu) {
            v.x = fmaxf(v.x, 0.f); v.y = fmaxf(v.y, 0.f);
            v.z = fmaxf(v.z, 0.f); v.w = fmaxf(v.w, 0.f);
        }
        acc.x += v.x; acc.y += v.y; acc.z += v.z; acc.w += v.w;
        cnt += 1.f;
        e = nx;
    }
    float sc = 1.0f / fmaxf(cnt, 1.0f);
    acc.x *= sc; acc.y *= sc; acc.z *= sc; acc.w *= sc;
    float* p = out + (size_t)warp * H + lane * 4;
    if (doRed) {
        asm volatile("red.global.add.v4.f32 [%0], {%1,%2,%3,%4};"
                     :: "l"(p), "f"(acc.x), "f"(acc.y), "f"(acc.z), "f"(acc.w) : "memory");
    } else {
        *(float4*)p = acc;
    }
}

// ---------------- final linear ----------------
__global__ void __launch_bounds__(128) final_kernel(
    const float* __restrict__ X, const float* __restrict__ W,
    const float* __restrict__ b, float* __restrict__ out, int M)
{
    __shared__ float Ws[H * 64];
    __shared__ float bs[64];
    for (int i = threadIdx.x; i < H * 64; i += 128) Ws[i] = W[i];
    if (threadIdx.x < 64) bs[threadIdx.x] = b[threadIdx.x];
    __syncthreads();
    int m = blockIdx.x * 128 + threadIdx.x;
    if (m >= M) return;
    float acc[64];
    #pragma unroll
    for (int j = 0; j < 64; j++) acc[j] = bs[j];
    const float* x = X + (size_t)m * H;
    for (int k = 0; k < H; k++) {
        float xv = fmaxf(x[k], 0.f);
        #pragma unroll
        for (int j = 0; j < 64; j++) acc[j] += xv * Ws[k * 64 + j];
    }
    float* o = out + (size_t)m * 64;
    #pragma unroll
    for (int j = 0; j < 64; j++) o[j] = acc[j];
}

// ---------------- host ----------------
static const int NN[NTYPE]   = {50000,2000,80000,10000,2000,150000,120000,100000,60000,40000};
static const int OFFS[NTYPE] = {0,50000,52000,132000,142000,144000,294000,414000,514000,574000};
static const int R_SRC[NREL] = {0,1,0,2,0,3,0,4,0,5,0,6,6,7,5,6,5,7,4,5,4,3,2,8,2,9};
static const int R_DST[NREL] = {1,0,2,0,3,0,4,0,5,0,6,0,7,6,6,5,7,5,5,4,3,4,8,2,9,2};
static const int R_EI[NREL]  = {10,10,11,11,12,12,13,13,14,14,15,15,16,16,17,17,18,18,19,19,20,20,21,21,22,22};
static const int R_FLIP[NREL]= {0,1,0,1,0,1,0,1,0,1,0,1,0,1,0,1,0,1,0,1,0,1,0,1,0,1};

// layer-1 needed dst types: all except reply(7), exercise(8), video(9)
static inline int l1_type_needed(int t) { return t < 7; }
static inline int l1_rel_needed(int r)  { return R_DST[r] < 7; }
// layer-2: only course(0)
static inline int l2_rel_needed(int r)  { return R_DST[r] == 0; }

extern "C" void kernel_launch(void* const* d_in, const int* in_sizes, int n_in,
                              void* d_out, int out_size)
{
    const float* Wl   = (const float*)d_in[23];
    const float* bl   = (const float*)d_in[24];
    const float* Wr   = (const float*)d_in[25];
    const float* linW = (const float*)d_in[26];
    const float* linb = (const float*)d_in[27];

    float *buf0, *buf1, *agg, *tmp, *wsum, *bsum;
    int *head, *nxt;
    __nv_bfloat16* wbf;
    cudaGetSymbolAddress((void**)&buf0, g_buf0);
    cudaGetSymbolAddress((void**)&buf1, g_buf1);
    cudaGetSymbolAddress((void**)&agg,  g_agg);
    cudaGetSymbolAddress((void**)&tmp,  g_tmp);
    cudaGetSymbolAddress((void**)&head, g_head);
    cudaGetSymbolAddress((void**)&nxt,  g_next);
    cudaGetSymbolAddress((void**)&wsum, g_wsum);
    cudaGetSymbolAddress((void**)&bsum, g_bsum);
    cudaGetSymbolAddress((void**)&wbf,  g_wbf);

    cudaFuncSetAttribute(gemm_mma, cudaFuncAttributeMaxDynamicSharedMemorySize, SM_BYTES);

    int DEGOFF[NREL], EOFF[NREL];
    {
        int a = 0, b2 = 0;
        for (int r = 0; r < NREL; r++) {
            DEGOFF[r] = a; a += NN[R_DST[r]];
            EOFF[r] = b2; b2 += in_sizes[R_EI[r]] / 2;
        }
    }

    // ---- prep: weights + chains (only for relations used by either layer) ----
    wsum_kernel<<<2 * NTYPE, 256>>>(Wr, bl, wsum, bsum);
    wcvt_kernel<<<72, 256>>>(wsum, Wl, wbf);
    cudaMemsetAsync(head, 0xFF, (size_t)DEG_TOTAL * sizeof(int), 0);
    for (int r = 0; r < NREL; r++) {
        if (!l1_rel_needed(r) && !l2_rel_needed(r)) continue;
        int ii = R_EI[r];
        const int* ei = (const int*)d_in[ii];
        int E = in_sizes[ii] / 2;
        const int* dstI = R_FLIP[r] ? ei : ei + E;
        build_chain_kernel<<<(E + 255) / 256, 256>>>(dstI, head + DEGOFF[r], nxt + EOFF[r], E);
    }

    const float* cur[NTYPE];
    for (int t = 0; t < NTYPE; t++) cur[t] = (const float*)d_in[t];
    float* bufs[2] = {buf0, buf1};

    for (int layer = 0; layer < 2; layer++) {
        float* outbuf = bufs[layer];
        const int lrelu = (layer == 1);

        // self term (pruned)
        for (int t = 0; t < NTYPE; t++) {
            if (layer == 0 ? !l1_type_needed(t) : (t != 0)) continue;
            gemm_mma<<<(NN[t] + 127) / 128, 512, SM_BYTES>>>(
                cur[t], wbf + (size_t)(layer * NTYPE + t) * 2 * H * H,
                bsum + ((size_t)layer * NTYPE + t) * H,
                outbuf + (size_t)OFFS[t] * H, NN[t], 0, lrelu);
        }

        // neighbor terms (pruned)
        for (int r = 0; r < NREL; r++) {
            if (layer == 0 ? !l1_rel_needed(r) : !l2_rel_needed(r)) continue;
            int s = R_SRC[r], d = R_DST[r], ii = R_EI[r];
            const int* ei = (const int*)d_in[ii];
            int E = in_sizes[ii] / 2;
            const int* srcI = R_FLIP[r] ? ei + E : ei;
            int nd = NN[d];
            const __nv_bfloat16* wmat = wbf + (size_t)(20 + layer * NREL + r) * 2 * H * H;
            unsigned ggrid = (unsigned)((nd + 7) / 8);

            if (NN[s] < nd) {
                gemm_mma<<<(NN[s] + 127) / 128, 512, SM_BYTES>>>(
                    cur[s], wmat, nullptr, tmp, NN[s], 0, lrelu);
                gather_kernel<<<ggrid, 256>>>(tmp, srcI, head + DEGOFF[r], nxt + EOFF[r],
                                              outbuf + (size_t)OFFS[d] * H, nd, 0, 1);
            } else {
                gather_kernel<<<ggrid, 256>>>(cur[s], srcI, head + DEGOFF[r], nxt + EOFF[r],
                                              agg, nd, lrelu, 0);
                gemm_mma<<<(nd + 127) / 128, 512, SM_BYTES>>>(
                    agg, wmat, nullptr, outbuf + (size_t)OFFS[d] * H, nd, 1, 0);
            }
        }

        for (int t = 0; t < NTYPE; t++) cur[t] = outbuf + (size_t)OFFS[t] * H;
    }

    final_kernel<<<(NN[0] + 127) / 128, 128>>>(cur[0], linW, linb, (float*)d_out, NN[0]);
}

// round 7
// speedup vs baseline: 4.8595x; 1.2899x over previous
#include <cuda_runtime.h>
#include <cuda_bf16.h>
#include <cstdint>
#include <cstddef>

#define H 128
#define NTYPE 10
#define NREL 26
#define MAX_DST 150000
#define DEG_TOTAL 1828000
#define EDGE_TOTAL (26 * 300000)
#define BUF0_ROWS 414000
#define BUF1_ROWS 50000
#define TMP_ROWS 600000
#define AGG_ROWS 300000

// ---------------- scratch ----------------
__device__ float g_buf0[(size_t)BUF0_ROWS * H];
__device__ float g_buf1[(size_t)BUF1_ROWS * H];
__device__ float g_agg[(size_t)AGG_ROWS * H];
__device__ float g_tmp[(size_t)TMP_ROWS * H];
__device__ int   g_head[DEG_TOTAL];
__device__ int   g_next[EDGE_TOTAL];
__device__ float g_wsum[2 * NTYPE * H * H];
__device__ float g_bsum[2 * NTYPE * H];
__device__ __nv_bfloat16 g_wbf[72 * 2 * H * H];

__constant__ int c_rel_dst[NREL] = {1,0,2,0,3,0,4,0,5,0,6,0,7,6,6,5,7,5,5,4,3,4,8,2,9,2};

// ---------------- job descriptors (passed by value) ----------------
struct GJob { const float* A; const __nv_bfloat16* Wb; const float* bias; float* C;
              int M; int tile_base; int flags; int _pad; };   // flags: 1=accum, 2=reluA
struct GBatch { GJob j[20]; int nj; };

struct SJob { const float* x; const int* srcI; const int* head; const int* next;
              float* out; int n; int node_base; int flags; }; // flags: 1=relu, 2=red
struct SBatch { SJob j[22]; int nj; };

struct CJob { const int* dstI; int* head; int* next; int E; int ebase; int _pad; };
struct CBatch { CJob j[22]; int nj; };

// ---------------- helpers ----------------
__device__ __forceinline__ uint32_t smem_to_u32(const void* p) {
    uint32_t a;
    asm("{ .reg .u64 t; cvta.to.shared.u64 t, %1; cvt.u32.u64 %0, t; }" : "=r"(a) : "l"(p));
    return a;
}

__device__ __forceinline__ void cvt8(const float* v, uint4& hi, uint4& lo) {
    uint32_t h[4], l[4];
    #pragma unroll
    for (int p = 0; p < 4; p++) {
        float a = v[2*p], b = v[2*p+1];
        __nv_bfloat16 ah = __float2bfloat16(a), bh = __float2bfloat16(b);
        float ar = a - __bfloat162float(ah), br = b - __bfloat162float(bh);
        __nv_bfloat16 al = __float2bfloat16(ar), bl2 = __float2bfloat16(br);
        h[p] = (uint32_t)__bfloat16_as_ushort(ah) | ((uint32_t)__bfloat16_as_ushort(bh) << 16);
        l[p] = (uint32_t)__bfloat16_as_ushort(al) | ((uint32_t)__bfloat16_as_ushort(bl2) << 16);
    }
    hi = make_uint4(h[0], h[1], h[2], h[3]);
    lo = make_uint4(l[0], l[1], l[2], l[3]);
}

#define LDMATRIX_X4(r0, r1, r2, r3, addr) \
    asm volatile("ldmatrix.sync.aligned.m8n8.x4.shared.b16 {%0,%1,%2,%3}, [%4];" \
                 : "=r"(r0), "=r"(r1), "=r"(r2), "=r"(r3) : "r"(addr))

#define MMA_BF16(c0, c1, c2, c3, a0, a1, a2, a3, b0, b1) \
    asm volatile("mma.sync.aligned.m16n8k16.row.col.f32.bf16.bf16.f32 " \
                 "{%0,%1,%2,%3}, {%4,%5,%6,%7}, {%8,%9}, {%0,%1,%2,%3};" \
                 : "+f"(c0), "+f"(c1), "+f"(c2), "+f"(c3) \
                 : "r"(a0), "r"(a1), "r"(a2), "r"(a3), "r"(b0), "r"(b1))

// ---------------- batched bf16 HMMA GEMM ----------------
#define A_LD 136
#define SM_AH 0
#define SM_AL 34816
#define SM_BH 69632
#define SM_BL 104448
#define SM_BYTES 139264

__global__ void __launch_bounds__(512) gemm_batched(GBatch bat)
{
    extern __shared__ char smem[];
    const uint32_t sb = smem_to_u32(smem);
    const int tid = threadIdx.x, lane = tid & 31, wid = tid >> 5;

    int jb = 0;
    while (jb + 1 < bat.nj && (int)blockIdx.x >= bat.j[jb + 1].tile_base) jb++;
    const GJob& J = bat.j[jb];
    const int m0 = (blockIdx.x - J.tile_base) * 128;
    const int M = J.M;
    const float* A = J.A;
    const float* bias = J.bias;
    float* C = J.C;
    const int accumulate = J.flags & 1;
    const int doRelu = J.flags & 2;

    // ---- stage A ----
    {
        const int r = tid >> 2;
        const int co = (tid & 3) * 32;
        const int m = m0 + r;
        if (m < M) {
            const float4* Ar = (const float4*)(A + (size_t)m * H);
            #pragma unroll
            for (int c = 0; c < 32; c += 8) {
                float4 f0 = Ar[(co + c) >> 2], f1 = Ar[((co + c) >> 2) + 1];
                float v[8] = {f0.x,f0.y,f0.z,f0.w,f1.x,f1.y,f1.z,f1.w};
                if (doRelu) {
                    #pragma unroll
                    for (int j = 0; j < 8; j++) v[j] = fmaxf(v[j], 0.f);
                }
                uint4 hi, lo;
                cvt8(v, hi, lo);
                *(uint4*)(smem + SM_AH + (size_t)(r * A_LD + co + c) * 2) = hi;
                *(uint4*)(smem + SM_AL + (size_t)(r * A_LD + co + c) * 2) = lo;
            }
        } else {
            uint4 z = make_uint4(0,0,0,0);
            #pragma unroll
            for (int c = 0; c < 32; c += 8) {
                *(uint4*)(smem + SM_AH + (size_t)(r * A_LD + co + c) * 2) = z;
                *(uint4*)(smem + SM_AL + (size_t)(r * A_LD + co + c) * 2) = z;
            }
        }
    }

    // ---- stage B ----
    {
        const uint4* srcH = (const uint4*)J.Wb;
        const uint4* srcL = srcH + 2048;
        #pragma unroll
        for (int it = 0; it < 4; it++) {
            int idx = tid + it * 512;
            int n = idx >> 4, q = idx & 15;
            *(uint4*)(smem + SM_BH + (size_t)n * (A_LD * 2) + q * 16) = srcH[idx];
            *(uint4*)(smem + SM_BL + (size_t)n * (A_LD * 2) + q * 16) = srcL[idx];
        }
    }
    __syncthreads();

    const int warp_m = (wid >> 2) * 32;
    const int warp_n = (wid & 3) * 32;

    float acc[2][4][4];
    #pragma unroll
    for (int mt = 0; mt < 2; mt++)
        #pragma unroll
        for (int nt = 0; nt < 4; nt++)
            #pragma unroll
            for (int q = 0; q < 4; q++) acc[mt][nt][q] = 0.0f;

    const int lrow = lane & 15;
    const int lcol = (lane >> 4) << 3;

    #pragma unroll
    for (int pass = 0; pass < 3; pass++) {
        const uint32_t abase = sb + (pass == 1 ? SM_AL : SM_AH);
        const uint32_t bbase = sb + (pass == 2 ? SM_BL : SM_BH);
        #pragma unroll
        for (int ks = 0; ks < 8; ks++) {
            const int k0 = ks * 16;
            uint32_t b[8];
            #pragma unroll
            for (int np = 0; np < 2; np++) {
                uint32_t addr = bbase + (uint32_t)(((warp_n + np * 16 + lrow) * A_LD + k0 + lcol) * 2);
                LDMATRIX_X4(b[np*4+0], b[np*4+1], b[np*4+2], b[np*4+3], addr);
            }
            #pragma unroll
            for (int mt = 0; mt < 2; mt++) {
                uint32_t a0, a1, a2, a3;
                uint32_t addr = abase + (uint32_t)(((warp_m + mt * 16 + lrow) * A_LD + k0 + lcol) * 2);
                LDMATRIX_X4(a0, a1, a2, a3, addr);
                MMA_BF16(acc[mt][0][0], acc[mt][0][1], acc[mt][0][2], acc[mt][0][3], a0, a1, a2, a3, b[0], b[2]);
                MMA_BF16(acc[mt][1][0], acc[mt][1][1], acc[mt][1][2], acc[mt][1][3], a0, a1, a2, a3, b[1], b[3]);
                MMA_BF16(acc[mt][2][0], acc[mt][2][1], acc[mt][2][2], acc[mt][2][3], a0, a1, a2, a3, b[4], b[6]);
                MMA_BF16(acc[mt][3][0], acc[mt][3][1], acc[mt][3][2], acc[mt][3][3], a0, a1, a2, a3, b[5], b[7]);
            }
        }
    }

    const int qrow = lane >> 2;
    const int qcol = (lane & 3) * 2;
    #pragma unroll
    for (int mt = 0; mt < 2; mt++) {
        #pragma unroll
        for (int half = 0; half < 2; half++) {
            const int m = m0 + warp_m + mt * 16 + qrow + half * 8;
            if (m < M) {
                float* cp = C + (size_t)m * H;
                #pragma unroll
                for (int nt = 0; nt < 4; nt++) {
                    const int c = warp_n + nt * 8 + qcol;
                    float v0 = acc[mt][nt][half * 2 + 0];
                    float v1 = acc[mt][nt][half * 2 + 1];
                    if (accumulate) {
                        asm volatile("red.global.add.v2.f32 [%0], {%1,%2};"
                                     :: "l"(cp + c), "f"(v0), "f"(v1) : "memory");
                    } else {
                        if (bias) { v0 += bias[c]; v1 += bias[c + 1]; }
                        *(float2*)(cp + c) = make_float2(v0, v1);
                    }
                }
            }
        }
    }
}

// ---------------- Wr / bias reduction ----------------
__global__ void __launch_bounds__(256) wsum_kernel(
    const float* __restrict__ Wr, const float* __restrict__ bl,
    float* __restrict__ wsum, float* __restrict__ bsum)
{
    int layer = blockIdx.x / NTYPE;
    int t = blockIdx.x % NTYPE;
    const float* base = Wr + (size_t)layer * NREL * H * H;
    float* outw = wsum + ((size_t)layer * NTYPE + t) * H * H;
    for (int e = threadIdx.x; e < H * H; e += 256) {
        float a = 0.f;
        #pragma unroll
        for (int r = 0; r < NREL; r++)
            if (c_rel_dst[r] == t) a += base[(size_t)r * H * H + e];
        outw[e] = a;
    }
    if (threadIdx.x < H) {
        float a = 0.f;
        #pragma unroll
        for (int r = 0; r < NREL; r++)
            if (c_rel_dst[r] == t) a += bl[((size_t)layer * NREL + r) * H + threadIdx.x];
        bsum[((size_t)layer * NTYPE + t) * H + threadIdx.x] = a;
    }
}

// ---------------- weight conversion ----------------
__global__ void __launch_bounds__(256) wcvt_kernel(
    const float* __restrict__ wsum, const float* __restrict__ Wl,
    __nv_bfloat16* __restrict__ wbf)
{
    int m = blockIdx.x;   // 0..71
    const float* src = (m < 20) ? (wsum + (size_t)m * H * H)
                                : (Wl + (size_t)(m - 20) * H * H);
    __nv_bfloat16* hi = wbf + (size_t)m * 2 * H * H;
    __nv_bfloat16* lo = hi + H * H;
    for (int idx = threadIdx.x; idx < H * H; idx += 256) {
        int k = idx >> 7, n = idx & 127;
        float w = src[idx];
        __nv_bfloat16 wh = __float2bfloat16(w);
        float wr = w - __bfloat162float(wh);
        hi[n * H + k] = wh;
        lo[n * H + k] = __float2bfloat16(wr);
    }
}

// ---------------- batched chain build ----------------
__global__ void __launch_bounds__(256) build_chain_batched(CBatch bat, int total)
{
    int g = blockIdx.x * blockDim.x + threadIdx.x;
    if (g >= total) return;
    int jb = 0;
    while (jb + 1 < bat.nj && g >= bat.j[jb + 1].ebase) jb++;
    const CJob& J = bat.j[jb];
    int e = g - J.ebase;
    J.next[e] = atomicExch(J.head + __ldg(J.dstI + e), e);
}

// ---------------- batched chain gather ----------------
__global__ void __launch_bounds__(256) gather_batched(SBatch bat, int total)
{
    int gw = blockIdx.x * (blockDim.x >> 5) + (threadIdx.x >> 5);
    if (gw >= total) return;
    int jb = 0;
    while (jb + 1 < bat.nj && gw >= bat.j[jb + 1].node_base) jb++;
    const SJob& J = bat.j[jb];
    const int node = gw - J.node_base;
    const int lane = threadIdx.x & 31;
    const int doRelu = J.flags & 1;
    const int doRed = J.flags & 2;
    const float* x = J.x;
    const int* srcI = J.srcI;
    const int* next = J.next;

    int e = __ldg(J.head + node);
    float4 acc = make_float4(0.f, 0.f, 0.f, 0.f);
    float cnt = 0.f;
    while (e >= 0) {
        int s  = __ldg(srcI + e);
        int nx = __ldg(next + e);
        float4 v = __ldg(((const float4*)(x + (size_t)s * H)) + lane);
        if (doRelu) {
            v.x = fmaxf(v.x, 0.f); v.y = fmaxf(v.y, 0.f);
            v.z = fmaxf(v.z, 0.f); v.w = fmaxf(v.w, 0.f);
        }
        acc.x += v.x; acc.y += v.y; acc.z += v.z; acc.w += v.w;
        cnt += 1.f;
        e = nx;
    }
    float sc = 1.0f / fmaxf(cnt, 1.0f);
    acc.x *= sc; acc.y *= sc; acc.z *= sc; acc.w *= sc;
    float* p = J.out + (size_t)node * H + lane * 4;
    if (doRed) {
        asm volatile("red.global.add.v4.f32 [%0], {%1,%2,%3,%4};"
                     :: "l"(p), "f"(acc.x), "f"(acc.y), "f"(acc.z), "f"(acc.w) : "memory");
    } else {
        *(float4*)p = acc;
    }
}

// ---------------- final linear ----------------
__global__ void __launch_bounds__(128) final_kernel(
    const float* __restrict__ X, const float* __restrict__ W,
    const float* __restrict__ b, float* __restrict__ out, int M)
{
    __shared__ float Ws[H * 64];
    __shared__ float bs[64];
    for (int i = threadIdx.x; i < H * 64; i += 128) Ws[i] = W[i];
    if (threadIdx.x < 64) bs[threadIdx.x] = b[threadIdx.x];
    __syncthreads();
    int m = blockIdx.x * 128 + threadIdx.x;
    if (m >= M) return;
    float acc[64];
    #pragma unroll
    for (int j = 0; j < 64; j++) acc[j] = bs[j];
    const float* x = X + (size_t)m * H;
    for (int k = 0; k < H; k++) {
        float xv = fmaxf(x[k], 0.f);
        #pragma unroll
        for (int j = 0; j < 64; j++) acc[j] += xv * Ws[k * 64 + j];
    }
    float* o = out + (size_t)m * 64;
    #pragma unroll
    for (int j = 0; j < 64; j++) o[j] = acc[j];
}

// ---------------- host ----------------
static const int NN[NTYPE]   = {50000,2000,80000,10000,2000,150000,120000,100000,60000,40000};
static const int OFFS[NTYPE] = {0,50000,52000,132000,142000,144000,294000,414000,514000,574000};
static const int R_SRC[NREL] = {0,1,0,2,0,3,0,4,0,5,0,6,6,7,5,6,5,7,4,5,4,3,2,8,2,9};
static const int R_DST[NREL] = {1,0,2,0,3,0,4,0,5,0,6,0,7,6,6,5,7,5,5,4,3,4,8,2,9,2};
static const int R_EI[NREL]  = {10,10,11,11,12,12,13,13,14,14,15,15,16,16,17,17,18,18,19,19,20,20,21,21,22,22};
static const int R_FLIP[NREL]= {0,1,0,1,0,1,0,1,0,1,0,1,0,1,0,1,0,1,0,1,0,1,0,1,0,1};

static inline int l1_type_needed(int t) { return t < 7; }
static inline int l1_rel_needed(int r)  { return R_DST[r] < 7; }
static inline int l2_rel_needed(int r)  { return R_DST[r] == 0; }

extern "C" void kernel_launch(void* const* d_in, const int* in_sizes, int n_in,
                              void* d_out, int out_size)
{
    const float* Wl   = (const float*)d_in[23];
    const float* bl   = (const float*)d_in[24];
    const float* Wr   = (const float*)d_in[25];
    const float* linW = (const float*)d_in[26];
    const float* linb = (const float*)d_in[27];

    float *buf0, *buf1, *agg, *tmp, *wsum, *bsum;
    int *head, *nxt;
    __nv_bfloat16* wbf;
    cudaGetSymbolAddress((void**)&buf0, g_buf0);
    cudaGetSymbolAddress((void**)&buf1, g_buf1);
    cudaGetSymbolAddress((void**)&agg,  g_agg);
    cudaGetSymbolAddress((void**)&tmp,  g_tmp);
    cudaGetSymbolAddress((void**)&head, g_head);
    cudaGetSymbolAddress((void**)&nxt,  g_next);
    cudaGetSymbolAddress((void**)&wsum, g_wsum);
    cudaGetSymbolAddress((void**)&bsum, g_bsum);
    cudaGetSymbolAddress((void**)&wbf,  g_wbf);

    cudaFuncSetAttribute(gemm_batched, cudaFuncAttributeMaxDynamicSharedMemorySize, SM_BYTES);

    int DEGOFF[NREL], EOFF[NREL];
    {
        int a = 0, b2 = 0;
        for (int r = 0; r < NREL; r++) {
            DEGOFF[r] = a; a += NN[R_DST[r]];
            EOFF[r] = b2; b2 += in_sizes[R_EI[r]] / 2;
        }
    }

    // ---- prep ----
    wsum_kernel<<<2 * NTYPE, 256>>>(Wr, bl, wsum, bsum);
    wcvt_kernel<<<72, 256>>>(wsum, Wl, wbf);
    cudaMemsetAsync(head, 0xFF, (size_t)DEG_TOTAL * sizeof(int), 0);

    {
        CBatch cb; cb.nj = 0;
        int etot = 0;
        for (int r = 0; r < NREL; r++) {
            if (!l1_rel_needed(r) && !l2_rel_needed(r)) continue;
            int ii = R_EI[r];
            const int* ei = (const int*)d_in[ii];
            int E = in_sizes[ii] / 2;
            const int* dstI = R_FLIP[r] ? ei : ei + E;
            CJob& J = cb.j[cb.nj++];
            J.dstI = dstI; J.head = head + DEGOFF[r]; J.next = nxt + EOFF[r];
            J.E = E; J.ebase = etot;
            etot += E;
        }
        build_chain_batched<<<(etot + 255) / 256, 256>>>(cb, etot);
    }

    const float* cur[NTYPE];
    for (int t = 0; t < NTYPE; t++) cur[t] = (const float*)d_in[t];
    float* bufs[2] = {buf0, buf1};

    for (int layer = 0; layer < 2; layer++) {
        float* outbuf = bufs[layer];
        const int lrelu = (layer == 1);
        const int aflags = lrelu ? 2 : 0;

        GBatch ga; ga.nj = 0; int gaTiles = 0;
        SBatch sb; sb.nj = 0; int sbNodes = 0;
        GBatch gb; gb.nj = 0; int gbTiles = 0;
        size_t tmpoff = 0, aggoff = 0;
        const float* tmpPtr[NREL];

        // ---- launch A jobs: self terms ----
        for (int t = 0; t < NTYPE; t++) {
            if (layer == 0 ? !l1_type_needed(t) : (t != 0)) continue;
            int outoff = (layer == 0) ? OFFS[t] : 0;
            GJob& J = ga.j[ga.nj++];
            J.A = cur[t];
            J.Wb = wbf + (size_t)(layer * NTYPE + t) * 2 * H * H;
            J.bias = bsum + ((size_t)layer * NTYPE + t) * H;
            J.C = outbuf + (size_t)outoff * H;
            J.M = NN[t]; J.tile_base = gaTiles; J.flags = aflags;
            gaTiles += (NN[t] + 127) / 128;
        }

        // ---- per relation: A-jobs (src transforms), gather jobs, B-jobs ----
        for (int r = 0; r < NREL; r++) {
            if (layer == 0 ? !l1_rel_needed(r) : !l2_rel_needed(r)) continue;
            int s = R_SRC[r], d = R_DST[r], ii = R_EI[r];
            const int* ei = (const int*)d_in[ii];
            int E = in_sizes[ii] / 2;
            const int* srcI = R_FLIP[r] ? ei + E : ei;
            int nd = NN[d];
            int outoff = (layer == 0) ? OFFS[d] : 0;
            const __nv_bfloat16* wmat = wbf + (size_t)(20 + layer * NREL + r) * 2 * H * H;

            if (NN[s] < nd) {
                // src-side: GEMM into tmp arena (launch A), then gather-red (launch S)
                float* tp = tmp + tmpoff * H;
                tmpoff += NN[s];
                tmpPtr[r] = tp;
                GJob& J = ga.j[ga.nj++];
                J.A = cur[s]; J.Wb = wmat; J.bias = nullptr; J.C = tp;
                J.M = NN[s]; J.tile_base = gaTiles; J.flags = aflags;
                gaTiles += (NN[s] + 127) / 128;

                SJob& S = sb.j[sb.nj++];
                S.x = tp; S.srcI = srcI; S.head = head + DEGOFF[r]; S.next = nxt + EOFF[r];
                S.out = outbuf + (size_t)outoff * H; S.n = nd;
                S.node_base = sbNodes; S.flags = 2;   // red, no relu (tmp is post-GEMM)
                sbNodes += nd;
            } else {
                // dst-side: gather mean into agg arena (launch S), then GEMM-red (launch B)
                float* ap = agg + aggoff * H;
                aggoff += nd;
                SJob& S = sb.j[sb.nj++];
                S.x = cur[s]; S.srcI = srcI; S.head = head + DEGOFF[r]; S.next = nxt + EOFF[r];
                S.out = ap; S.n = nd;
                S.node_base = sbNodes; S.flags = lrelu ? 1 : 0;  // store, relu on input if layer2
                sbNodes += nd;

                GJob& J = gb.j[gb.nj++];
                J.A = ap; J.Wb = wmat; J.bias = nullptr;
                J.C = outbuf + (size_t)outoff * H;
                J.M = nd; J.tile_base = gbTiles; J.flags = 1;   // accumulate
                gbTiles += (nd + 127) / 128;
            }
        }

        gemm_batched<<<gaTiles, 512, SM_BYTES>>>(ga);
        gather_batched<<<(sbNodes + 7) / 8, 256>>>(sb, sbNodes);
        gemm_batched<<<gbTiles, 512, SM_BYTES>>>(gb);

        if (layer == 0)
            for (int t = 0; t < 7; t++) cur[t] = buf0 + (size_t)OFFS[t] * H;
    }

    final_kernel<<<(BUF1_ROWS + 127) / 128, 128>>>(buf1, linW, linb, (float*)d_out, BUF1_ROWS);
}

// round 8
// speedup vs baseline: 5.3562x; 1.1022x over previous
#include <cuda_runtime.h>
#include <cuda_bf16.h>
#include <cstdint>
#include <cstddef>

#define H 128
#define NTYPE 10
#define NREL 26
#define DEG_TOTAL 1828000
#define EDGE_TOTAL (26 * 300000)
#define BUF0_ROWS 414000
#define BUF1_ROWS 50000
#define TMP_ROWS 600000
#define AGG_ROWS 300000

// ---------------- scratch ----------------
__device__ float g_buf0[(size_t)BUF0_ROWS * H];
__device__ float g_buf1[(size_t)BUF1_ROWS * H];
__device__ float g_agg[(size_t)AGG_ROWS * H];     // also used as bf16 hi/lo plane arena
__device__ float g_tmp[(size_t)TMP_ROWS * H];
__device__ int   g_head[DEG_TOTAL];
__device__ int   g_next[EDGE_TOTAL];
__device__ float g_wsum[2 * NTYPE * H * H];
__device__ float g_bsum[2 * NTYPE * H];
__device__ __nv_bfloat16 g_wbf[72 * 2 * H * H];

__constant__ int c_rel_dst[NREL] = {1,0,2,0,3,0,4,0,5,0,6,0,7,6,6,5,7,5,5,4,3,4,8,2,9,2};

// ---------------- job descriptors ----------------
// GJob flags: 1=accumulate(red), 2=relu on A load, 4=A is pre-split bf16 planes
struct GJob { const float* A; const __nv_bfloat16* Wb; const float* bias; float* C;
              int M; int tile_base; int flags; int _pad; };
struct GBatch { GJob j[20]; int nj; };

// SJob flags: 1=relu on x, 2=red-accumulate fp32 out, 4=write pre-split bf16 planes
struct SJob { const float* x; const int* srcI; const int* head; const int* next;
              float* out; int n; int node_base; int flags; };
struct SBatch { SJob j[22]; int nj; };

struct CJob { const int* dstI; int* head; int* next; int E; int ebase; int _pad; };
struct CBatch { CJob j[22]; int nj; };

// ---------------- helpers ----------------
__device__ __forceinline__ uint32_t smem_to_u32(const void* p) {
    uint32_t a;
    asm("{ .reg .u64 t; cvta.to.shared.u64 t, %1; cvt.u32.u64 %0, t; }" : "=r"(a) : "l"(p));
    return a;
}

__device__ __forceinline__ void cvt8(const float* v, uint4& hi, uint4& lo) {
    uint32_t h[4], l[4];
    #pragma unroll
    for (int p = 0; p < 4; p++) {
        float a = v[2*p], b = v[2*p+1];
        __nv_bfloat16 ah = __float2bfloat16(a), bh = __float2bfloat16(b);
        float ar = a - __bfloat162float(ah), br = b - __bfloat162float(bh);
        __nv_bfloat16 al = __float2bfloat16(ar), bl2 = __float2bfloat16(br);
        h[p] = (uint32_t)__bfloat16_as_ushort(ah) | ((uint32_t)__bfloat16_as_ushort(bh) << 16);
        l[p] = (uint32_t)__bfloat16_as_ushort(al) | ((uint32_t)__bfloat16_as_ushort(bl2) << 16);
    }
    hi = make_uint4(h[0], h[1], h[2], h[3]);
    lo = make_uint4(l[0], l[1], l[2], l[3]);
}

#define LDMATRIX_X4(r0, r1, r2, r3, addr) \
    asm volatile("ldmatrix.sync.aligned.m8n8.x4.shared.b16 {%0,%1,%2,%3}, [%4];" \
                 : "=r"(r0), "=r"(r1), "=r"(r2), "=r"(r3) : "r"(addr))

#define MMA_BF16(c0, c1, c2, c3, a0, a1, a2, a3, b0, b1) \
    asm volatile("mma.sync.aligned.m16n8k16.row.col.f32.bf16.bf16.f32 " \
                 "{%0,%1,%2,%3}, {%4,%5,%6,%7}, {%8,%9}, {%0,%1,%2,%3};" \
                 : "+f"(c0), "+f"(c1), "+f"(c2), "+f"(c3) \
                 : "r"(a0), "r"(a1), "r"(a2), "r"(a3), "r"(b0), "r"(b1))

// ---------------- batched bf16 HMMA GEMM: 64x128 tile, 256 thr, 2 CTA/SM ----------------
#define A_LD 136
#define SM_AH 0
#define SM_AL 17408
#define SM_BH 34816
#define SM_BL 69632
#define SM_BYTES 104448

__global__ void __launch_bounds__(256, 2) gemm_batched(GBatch bat)
{
    extern __shared__ char smem[];
    const uint32_t sb = smem_to_u32(smem);
    const int tid = threadIdx.x, lane = tid & 31, wid = tid >> 5;

    int jb = 0;
    while (jb + 1 < bat.nj && (int)blockIdx.x >= bat.j[jb + 1].tile_base) jb++;
    const GJob& J = bat.j[jb];
    const int m0 = (blockIdx.x - J.tile_base) * 64;
    const int M = J.M;
    const int accumulate = J.flags & 1;
    const int doRelu = J.flags & 2;
    const int presplit = J.flags & 4;
    const float* bias = J.bias;
    float* C = J.C;

    // ---- stage A (64 rows) ----
    if (presplit) {
        // A points at bf16 hi plane [M][128]; lo plane follows at +M*128 elems
        const uint4* srcH = (const uint4*)J.A + (size_t)m0 * 16;
        const uint4* srcL = (const uint4*)((const __nv_bfloat16*)J.A + (size_t)M * H) + (size_t)m0 * 16;
        #pragma unroll
        for (int it = 0; it < 4; it++) {
            int idx = tid + it * 256;          // 1024 uint4 per plane
            int n = idx >> 4, q = idx & 15;
            *(uint4*)(smem + SM_AH + (size_t)n * (A_LD * 2) + q * 16) = srcH[idx];
            *(uint4*)(smem + SM_AL + (size_t)n * (A_LD * 2) + q * 16) = srcL[idx];
        }
    } else {
        const int r = tid >> 2;                // 0..63
        const int co = (tid & 3) * 32;
        const int m = m0 + r;
        if (m < M) {
            const float4* Ar = (const float4*)(J.A + (size_t)m * H);
            #pragma unroll
            for (int c = 0; c < 32; c += 8) {
                float4 f0 = Ar[(co + c) >> 2], f1 = Ar[((co + c) >> 2) + 1];
                float v[8] = {f0.x,f0.y,f0.z,f0.w,f1.x,f1.y,f1.z,f1.w};
                if (doRelu) {
                    #pragma unroll
                    for (int j = 0; j < 8; j++) v[j] = fmaxf(v[j], 0.f);
                }
                uint4 hi, lo;
                cvt8(v, hi, lo);
                *(uint4*)(smem + SM_AH + (size_t)(r * A_LD + co + c) * 2) = hi;
                *(uint4*)(smem + SM_AL + (size_t)(r * A_LD + co + c) * 2) = lo;
            }
        } else {
            uint4 z = make_uint4(0,0,0,0);
            #pragma unroll
            for (int c = 0; c < 32; c += 8) {
                *(uint4*)(smem + SM_AH + (size_t)(r * A_LD + co + c) * 2) = z;
                *(uint4*)(smem + SM_AL + (size_t)(r * A_LD + co + c) * 2) = z;
            }
        }
    }

    // ---- stage B: 2048 uint4 per plane ----
    {
        const uint4* srcH = (const uint4*)J.Wb;
        const uint4* srcL = srcH + 2048;
        #pragma unroll
        for (int it = 0; it < 8; it++) {
            int idx = tid + it * 256;
            int n = idx >> 4, q = idx & 15;
            *(uint4*)(smem + SM_BH + (size_t)n * (A_LD * 2) + q * 16) = srcH[idx];
            *(uint4*)(smem + SM_BL + (size_t)n * (A_LD * 2) + q * 16) = srcL[idx];
        }
    }
    __syncthreads();

    // ---- warp tiling: 2x4 warps, each 32(m) x 32(n) ----
    const int warp_m = (wid >> 2) * 32;
    const int warp_n = (wid & 3) * 32;

    float acc[2][4][4];
    #pragma unroll
    for (int mt = 0; mt < 2; mt++)
        #pragma unroll
        for (int nt = 0; nt < 4; nt++)
            #pragma unroll
            for (int q = 0; q < 4; q++) acc[mt][nt][q] = 0.0f;

    const int lrow = lane & 15;
    const int lcol = (lane >> 4) << 3;

    // precomputed byte offsets within a plane (add ks*32 per k-slice)
    uint32_t aoff[2], boff[2];
    #pragma unroll
    for (int mt = 0; mt < 2; mt++)
        aoff[mt] = (uint32_t)(((warp_m + mt * 16 + lrow) * A_LD + lcol) * 2);
    #pragma unroll
    for (int np = 0; np < 2; np++)
        boff[np] = (uint32_t)(((warp_n + np * 16 + lrow) * A_LD + lcol) * 2);

    #pragma unroll
    for (int ks = 0; ks < 8; ks++) {
        const uint32_t kb = ks * 32;
        uint32_t bh[8], bl[8], ah[2][4], al[2][4];
        #pragma unroll
        for (int np = 0; np < 2; np++) {
            LDMATRIX_X4(bh[np*4+0], bh[np*4+1], bh[np*4+2], bh[np*4+3], sb + SM_BH + boff[np] + kb);
            LDMATRIX_X4(bl[np*4+0], bl[np*4+1], bl[np*4+2], bl[np*4+3], sb + SM_BL + boff[np] + kb);
        }
        #pragma unroll
        for (int mt = 0; mt < 2; mt++) {
            LDMATRIX_X4(ah[mt][0], ah[mt][1], ah[mt][2], ah[mt][3], sb + SM_AH + aoff[mt] + kb);
            LDMATRIX_X4(al[mt][0], al[mt][1], al[mt][2], al[mt][3], sb + SM_AL + aoff[mt] + kb);
        }
        #pragma unroll
        for (int mt = 0; mt < 2; mt++) {
            // hh
            MMA_BF16(acc[mt][0][0], acc[mt][0][1], acc[mt][0][2], acc[mt][0][3], ah[mt][0], ah[mt][1], ah[mt][2], ah[mt][3], bh[0], bh[2]);
            MMA_BF16(acc[mt][1][0], acc[mt][1][1], acc[mt][1][2], acc[mt][1][3], ah[mt][0], ah[mt][1], ah[mt][2], ah[mt][3], bh[1], bh[3]);
            MMA_BF16(acc[mt][2][0], acc[mt][2][1], acc[mt][2][2], acc[mt][2][3], ah[mt][0], ah[mt][1], ah[mt][2], ah[mt][3], bh[4], bh[6]);
            MMA_BF16(acc[mt][3][0], acc[mt][3][1], acc[mt][3][2], acc[mt][3][3], ah[mt][0], ah[mt][1], ah[mt][2], ah[mt][3], bh[5], bh[7]);
            // lh
            MMA_BF16(acc[mt][0][0], acc[mt][0][1], acc[mt][0][2], acc[mt][0][3], al[mt][0], al[mt][1], al[mt][2], al[mt][3], bh[0], bh[2]);
            MMA_BF16(acc[mt][1][0], acc[mt][1][1], acc[mt][1][2], acc[mt][1][3], al[mt][0], al[mt][1], al[mt][2], al[mt][3], bh[1], bh[3]);
            MMA_BF16(acc[mt][2][0], acc[mt][2][1], acc[mt][2][2], acc[mt][2][3], al[mt][0], al[mt][1], al[mt][2], al[mt][3], bh[4], bh[6]);
            MMA_BF16(acc[mt][3][0], acc[mt][3][1], acc[mt][3][2], acc[mt][3][3], al[mt][0], al[mt][1], al[mt][2], al[mt][3], bh[5], bh[7]);
            // hl
            MMA_BF16(acc[mt][0][0], acc[mt][0][1], acc[mt][0][2], acc[mt][0][3], ah[mt][0], ah[mt][1], ah[mt][2], ah[mt][3], bl[0], bl[2]);
            MMA_BF16(acc[mt][1][0], acc[mt][1][1], acc[mt][1][2], acc[mt][1][3], ah[mt][0], ah[mt][1], ah[mt][2], ah[mt][3], bl[1], bl[3]);
            MMA_BF16(acc[mt][2][0], acc[mt][2][1], acc[mt][2][2], acc[mt][2][3], ah[mt][0], ah[mt][1], ah[mt][2], ah[mt][3], bl[4], bl[6]);
            MMA_BF16(acc[mt][3][0], acc[mt][3][1], acc[mt][3][2], acc[mt][3][3], ah[mt][0], ah[mt][1], ah[mt][2], ah[mt][3], bl[5], bl[7]);
        }
    }

    // ---- epilogue ----
    const int qrow = lane >> 2;
    const int qcol = (lane & 3) * 2;
    #pragma unroll
    for (int mt = 0; mt < 2; mt++) {
        #pragma unroll
        for (int half = 0; half < 2; half++) {
            const int m = m0 + warp_m + mt * 16 + qrow + half * 8;
            if (m < M) {
                float* cp = C + (size_t)m * H;
                #pragma unroll
                for (int nt = 0; nt < 4; nt++) {
                    const int c = warp_n + nt * 8 + qcol;
                    float v0 = acc[mt][nt][half * 2 + 0];
                    float v1 = acc[mt][nt][half * 2 + 1];
                    if (accumulate) {
                        asm volatile("red.global.add.v2.f32 [%0], {%1,%2};"
                                     :: "l"(cp + c), "f"(v0), "f"(v1) : "memory");
                    } else {
                        if (bias) { v0 += bias[c]; v1 += bias[c + 1]; }
                        *(float2*)(cp + c) = make_float2(v0, v1);
                    }
                }
            }
        }
    }
}

// ---------------- Wr / bias reduction ----------------
__global__ void __launch_bounds__(256) wsum_kernel(
    const float* __restrict__ Wr, const float* __restrict__ bl,
    float* __restrict__ wsum, float* __restrict__ bsum)
{
    int layer = blockIdx.x / NTYPE;
    int t = blockIdx.x % NTYPE;
    const float* base = Wr + (size_t)layer * NREL * H * H;
    float* outw = wsum + ((size_t)layer * NTYPE + t) * H * H;
    for (int e = threadIdx.x; e < H * H; e += 256) {
        float a = 0.f;
        #pragma unroll
        for (int r = 0; r < NREL; r++)
            if (c_rel_dst[r] == t) a += base[(size_t)r * H * H + e];
        outw[e] = a;
    }
    if (threadIdx.x < H) {
        float a = 0.f;
        #pragma unroll
        for (int r = 0; r < NREL; r++)
            if (c_rel_dst[r] == t) a += bl[((size_t)layer * NREL + r) * H + threadIdx.x];
        bsum[((size_t)layer * NTYPE + t) * H + threadIdx.x] = a;
    }
}

// ---------------- weight conversion ----------------
__global__ void __launch_bounds__(256) wcvt_kernel(
    const float* __restrict__ wsum, const float* __restrict__ Wl,
    __nv_bfloat16* __restrict__ wbf)
{
    int m = blockIdx.x;   // 0..71
    const float* src = (m < 20) ? (wsum + (size_t)m * H * H)
                                : (Wl + (size_t)(m - 20) * H * H);
    __nv_bfloat16* hi = wbf + (size_t)m * 2 * H * H;
    __nv_bfloat16* lo = hi + H * H;
    for (int idx = threadIdx.x; idx < H * H; idx += 256) {
        int k = idx >> 7, n = idx & 127;
        float w = src[idx];
        __nv_bfloat16 wh = __float2bfloat16(w);
        float wr = w - __bfloat162float(wh);
        hi[n * H + k] = wh;
        lo[n * H + k] = __float2bfloat16(wr);
    }
}

// ---------------- batched chain build ----------------
__global__ void __launch_bounds__(256) build_chain_batched(CBatch bat, int total)
{
    int g = blockIdx.x * blockDim.x + threadIdx.x;
    if (g >= total) return;
    int jb = 0;
    while (jb + 1 < bat.nj && g >= bat.j[jb + 1].ebase) jb++;
    const CJob& J = bat.j[jb];
    int e = g - J.ebase;
    J.next[e] = atomicExch(J.head + __ldg(J.dstI + e), e);
}

// ---------------- batched chain gather ----------------
__global__ void __launch_bounds__(256) gather_batched(SBatch bat, int total)
{
    int gw = blockIdx.x * (blockDim.x >> 5) + (threadIdx.x >> 5);
    if (gw >= total) return;
    int jb = 0;
    while (jb + 1 < bat.nj && gw >= bat.j[jb + 1].node_base) jb++;
    const SJob& J = bat.j[jb];
    const int node = gw - J.node_base;
    const int lane = threadIdx.x & 31;
    const int doRelu = J.flags & 1;
    const float* x = J.x;
    const int* srcI = J.srcI;
    const int* next = J.next;

    int e = __ldg(J.head + node);
    float4 acc = make_float4(0.f, 0.f, 0.f, 0.f);
    float cnt = 0.f;
    while (e >= 0) {
        int s  = __ldg(srcI + e);
        int nx = __ldg(next + e);
        float4 v = __ldg(((const float4*)(x + (size_t)s * H)) + lane);
        if (doRelu) {
            v.x = fmaxf(v.x, 0.f); v.y = fmaxf(v.y, 0.f);
            v.z = fmaxf(v.z, 0.f); v.w = fmaxf(v.w, 0.f);
        }
        acc.x += v.x; acc.y += v.y; acc.z += v.z; acc.w += v.w;
        cnt += 1.f;
        e = nx;
    }
    float sc = 1.0f / fmaxf(cnt, 1.0f);
    acc.x *= sc; acc.y *= sc; acc.z *= sc; acc.w *= sc;

    if (J.flags & 4) {
        // write pre-split bf16 planes: hi at out, lo at out + n*128 (bf16 elems)
        float v[4] = {acc.x, acc.y, acc.z, acc.w};
        uint32_t h[2], l[2];
        #pragma unroll
        for (int p = 0; p < 2; p++) {
            float a = v[2*p], b = v[2*p+1];
            __nv_bfloat16 ah = __float2bfloat16(a), bh = __float2bfloat16(b);
            float ar = a - __bfloat162float(ah), br = b - __bfloat162float(bh);
            h[p] = (uint32_t)__bfloat16_as_ushort(ah) | ((uint32_t)__bfloat16_as_ushort(bh) << 16);
            l[p] = (uint32_t)__bfloat16_as_ushort(__float2bfloat16(ar))
                 | ((uint32_t)__bfloat16_as_ushort(__float2bfloat16(br)) << 16);
        }
        __nv_bfloat16* hi = (__nv_bfloat16*)J.out;
        *(uint2*)(hi + (size_t)node * H + lane * 4) = make_uint2(h[0], h[1]);
        *(uint2*)(hi + (size_t)J.n * H + (size_t)node * H + lane * 4) = make_uint2(l[0], l[1]);
    } else if (J.flags & 2) {
        float* p = J.out + (size_t)node * H + lane * 4;
        asm volatile("red.global.add.v4.f32 [%0], {%1,%2,%3,%4};"
                     :: "l"(p), "f"(acc.x), "f"(acc.y), "f"(acc.z), "f"(acc.w) : "memory");
    } else {
        *(float4*)(J.out + (size_t)node * H + lane * 4) = acc;
    }
}

// ---------------- final linear ----------------
__global__ void __launch_bounds__(128) final_kernel(
    const float* __restrict__ X, const float* __restrict__ W,
    const float* __restrict__ b, float* __restrict__ out, int M)
{
    __shared__ float Ws[H * 64];
    __shared__ float bs[64];
    for (int i = threadIdx.x; i < H * 64; i += 128) Ws[i] = W[i];
    if (threadIdx.x < 64) bs[threadIdx.x] = b[threadIdx.x];
    __syncthreads();
    int m = blockIdx.x * 128 + threadIdx.x;
    if (m >= M) return;
    float acc[64];
    #pragma unroll
    for (int j = 0; j < 64; j++) acc[j] = bs[j];
    const float* x = X + (size_t)m * H;
    for (int k = 0; k < H; k++) {
        float xv = fmaxf(x[k], 0.f);
        #pragma unroll
        for (int j = 0; j < 64; j++) acc[j] += xv * Ws[k * 64 + j];
    }
    float* o = out + (size_t)m * 64;
    #pragma unroll
    for (int j = 0; j < 64; j++) o[j] = acc[j];
}

// ---------------- host ----------------
static const int NN[NTYPE]   = {50000,2000,80000,10000,2000,150000,120000,100000,60000,40000};
static const int OFFS[NTYPE] = {0,50000,52000,132000,142000,144000,294000,414000,514000,574000};
static const int R_SRC[NREL] = {0,1,0,2,0,3,0,4,0,5,0,6,6,7,5,6,5,7,4,5,4,3,2,8,2,9};
static const int R_DST[NREL] = {1,0,2,0,3,0,4,0,5,0,6,0,7,6,6,5,7,5,5,4,3,4,8,2,9,2};
static const int R_EI[NREL]  = {10,10,11,11,12,12,13,13,14,14,15,15,16,16,17,17,18,18,19,19,20,20,21,21,22,22};
static const int R_FLIP[NREL]= {0,1,0,1,0,1,0,1,0,1,0,1,0,1,0,1,0,1,0,1,0,1,0,1,0,1};

static inline int l1_type_needed(int t) { return t < 7; }
static inline int l1_rel_needed(int r)  { return R_DST[r] < 7; }
static inline int l2_rel_needed(int r)  { return R_DST[r] == 0; }

extern "C" void kernel_launch(void* const* d_in, const int* in_sizes, int n_in,
                              void* d_out, int out_size)
{
    const float* Wl   = (const float*)d_in[23];
    const float* bl   = (const float*)d_in[24];
    const float* Wr   = (const float*)d_in[25];
    const float* linW = (const float*)d_in[26];
    const float* linb = (const float*)d_in[27];

    float *buf0, *buf1, *agg, *tmp, *wsum, *bsum;
    int *head, *nxt;
    __nv_bfloat16* wbf;
    cudaGetSymbolAddress((void**)&buf0, g_buf0);
    cudaGetSymbolAddress((void**)&buf1, g_buf1);
    cudaGetSymbolAddress((void**)&agg,  g_agg);
    cudaGetSymbolAddress((void**)&tmp,  g_tmp);
    cudaGetSymbolAddress((void**)&head, g_head);
    cudaGetSymbolAddress((void**)&nxt,  g_next);
    cudaGetSymbolAddress((void**)&wsum, g_wsum);
    cudaGetSymbolAddress((void**)&bsum, g_bsum);
    cudaGetSymbolAddress((void**)&wbf,  g_wbf);

    cudaFuncSetAttribute(gemm_batched, cudaFuncAttributeMaxDynamicSharedMemorySize, SM_BYTES);

    int DEGOFF[NREL], EOFF[NREL];
    {
        int a = 0, b2 = 0;
        for (int r = 0; r < NREL; r++) {
            DEGOFF[r] = a; a += NN[R_DST[r]];
            EOFF[r] = b2; b2 += in_sizes[R_EI[r]] / 2;
        }
    }

    // ---- prep ----
    wsum_kernel<<<2 * NTYPE, 256>>>(Wr, bl, wsum, bsum);
    wcvt_kernel<<<72, 256>>>(wsum, Wl, wbf);
    cudaMemsetAsync(head, 0xFF, (size_t)DEG_TOTAL * sizeof(int), 0);

    {
        CBatch cb; cb.nj = 0;
        int etot = 0;
        for (int r = 0; r < NREL; r++) {
            if (!l1_rel_needed(r) && !l2_rel_needed(r)) continue;
            int ii = R_EI[r];
            const int* ei = (const int*)d_in[ii];
            int E = in_sizes[ii] / 2;
            const int* dstI = R_FLIP[r] ? ei : ei + E;
            CJob& J = cb.j[cb.nj++];
            J.dstI = dstI; J.head = head + DEGOFF[r]; J.next = nxt + EOFF[r];
            J.E = E; J.ebase = etot;
            etot += E;
        }
        build_chain_batched<<<(etot + 255) / 256, 256>>>(cb, etot);
    }

    const float* cur[NTYPE];
    for (int t = 0; t < NTYPE; t++) cur[t] = (const float*)d_in[t];
    float* bufs[2] = {buf0, buf1};

    for (int layer = 0; layer < 2; layer++) {
        float* outbuf = bufs[layer];
        const int lrelu = (layer == 1);
        const int aflags = lrelu ? 2 : 0;

        GBatch ga; ga.nj = 0; int gaTiles = 0;
        SBatch sb; sb.nj = 0; int sbNodes = 0;
        GBatch gb; gb.nj = 0; int gbTiles = 0;
        size_t tmpoff = 0, aggoff = 0;

        // self terms
        for (int t = 0; t < NTYPE; t++) {
            if (layer == 0 ? !l1_type_needed(t) : (t != 0)) continue;
            int outoff = (layer == 0) ? OFFS[t] : 0;
            GJob& J = ga.j[ga.nj++];
            J.A = cur[t];
            J.Wb = wbf + (size_t)(layer * NTYPE + t) * 2 * H * H;
            J.bias = bsum + ((size_t)layer * NTYPE + t) * H;
            J.C = outbuf + (size_t)outoff * H;
            J.M = NN[t]; J.tile_base = gaTiles; J.flags = aflags;
            gaTiles += (NN[t] + 63) / 64;
        }

        // neighbor terms
        for (int r = 0; r < NREL; r++) {
            if (layer == 0 ? !l1_rel_needed(r) : !l2_rel_needed(r)) continue;
            int s = R_SRC[r], d = R_DST[r], ii = R_EI[r];
            const int* ei = (const int*)d_in[ii];
            int E = in_sizes[ii] / 2;
            const int* srcI = R_FLIP[r] ? ei + E : ei;
            int nd = NN[d];
            int outoff = (layer == 0) ? OFFS[d] : 0;
            const __nv_bfloat16* wmat = wbf + (size_t)(20 + layer * NREL + r) * 2 * H * H;

            if (NN[s] < nd) {
                // src-side: GEMM into tmp, gather-red into out
                float* tp = tmp + tmpoff * H;
                tmpoff += NN[s];
                GJob& J = ga.j[ga.nj++];
                J.A = cur[s]; J.Wb = wmat; J.bias = nullptr; J.C = tp;
                J.M = NN[s]; J.tile_base = gaTiles; J.flags = aflags;
                gaTiles += (NN[s] + 63) / 64;

                SJob& S = sb.j[sb.nj++];
                S.x = tp; S.srcI = srcI; S.head = head + DEGOFF[r]; S.next = nxt + EOFF[r];
                S.out = outbuf + (size_t)outoff * H; S.n = nd;
                S.node_base = sbNodes; S.flags = 2;   // red fp32
                sbNodes += nd;
            } else {
                // dst-side: gather mean -> pre-split bf16 planes, then GEMM-red
                float* ap = agg + aggoff * H;   // nd*512B footprint = nd*128 floats
                aggoff += nd;
                SJob& S = sb.j[sb.nj++];
                S.x = cur[s]; S.srcI = srcI; S.head = head + DEGOFF[r]; S.next = nxt + EOFF[r];
                S.out = ap; S.n = nd;
                S.node_base = sbNodes; S.flags = (lrelu ? 1 : 0) | 4;  // presplit write
                sbNodes += nd;

                GJob& J = gb.j[gb.nj++];
                J.A = ap; J.Wb = wmat; J.bias = nullptr;
                J.C = outbuf + (size_t)outoff * H;
                J.M = nd; J.tile_base = gbTiles; J.flags = 1 | 4;  // accumulate, presplit A
                gbTiles += (nd + 63) / 64;
            }
        }

        gemm_batched<<<gaTiles, 256, SM_BYTES>>>(ga);
        gather_batched<<<(sbNodes + 7) / 8, 256>>>(sb, sbNodes);
        gemm_batched<<<gbTiles, 256, SM_BYTES>>>(gb);

        if (layer == 0)
            for (int t = 0; t < 7; t++) cur[t] = buf0 + (size_t)OFFS[t] * H;
    }

    final_kernel<<<(BUF1_ROWS + 127) / 128, 128>>>(buf1, linW, linb, (float*)d_out, BUF1_ROWS);
}